// round 4
// baseline (speedup 1.0000x reference)
#include <cuda_runtime.h>
#include <math.h>

#define NL 1200          // lines per set
#define S  5             // NUM_SAMPLES
#define NS (NL*S)        // 6000 samples per set
#define DD 128           // descriptor dim
#define HW 128           // feature map H=W
#define TOPK 10
#define GAPP 0.1f

// ---------------- scratch (no allocs allowed) ----------------
__device__ float g_pts[2*NS*2];        // (y,x) per sample
__device__ int   g_valid[2*NS];
__device__ float g_desc[2*NS*DD];      // normalized descriptors, sample-major
__device__ float g_ls[NL*NL];          // line_scores (dir1); dir2 is its transpose
__device__ int   g_topk[2*NL*TOPK];
__device__ float g_nwout[NL*2*TOPK];   // nw for direction 1 (the returned one)
__device__ int   g_matches[2*NL];

// ---------------- 1) sample line points (XLA-exact: no FMA contraction) ----------------
__global__ void k_points(const float* __restrict__ seg1,
                         const float* __restrict__ seg2) {
    int l = blockIdx.x * blockDim.x + threadIdx.x;
    if (l >= 2*NL) return;
    const float* seg = (l < NL) ? (seg1 + l*4) : (seg2 + (l-NL)*4);
    float sy = seg[0], sx = seg[1], ey = seg[2], ex = seg[3];
    float dy = __fsub_rn(ey, sy), dx = __fsub_rn(ex, sx);
    // lengths = sqrt(dy^2 + dx^2): separate muls, one add, rn sqrt
    float len = __fsqrt_rn(__fadd_rn(__fmul_rn(dy, dy), __fmul_rn(dx, dx)));
    float ns = floorf(__fdiv_rn(len, 8.0f));
    ns = fminf(fmaxf(ns, 2.0f), 5.0f);
    float den = __fsub_rn(ns, 1.0f);
    float ivy = __fdiv_rn(dy, den);
    float ivx = __fdiv_rn(dx, den);
    #pragma unroll
    for (int k = 0; k < S; k++) {
        bool v = ((float)k < ns);
        // pts = start + k*interval: separate mul, add (no FMA)
        float py = __fadd_rn(sy, __fmul_rn((float)k, ivy));
        float px = __fadd_rn(sx, __fmul_rn((float)k, ivx));
        g_pts[(l*S + k)*2 + 0] = v ? py : 0.0f;
        g_pts[(l*S + k)*2 + 1] = v ? px : 0.0f;
        g_valid[l*S + k] = v ? 1 : 0;
    }
}

// ---------------- 2) bilinear descriptor sampling + L2 normalize (XLA-exact) ----------------
__global__ void k_sample(const float* __restrict__ desc1,
                         const float* __restrict__ desc2) {
    int p = blockIdx.x;              // 0..2*NS-1
    int d = threadIdx.x;             // 0..127
    const float* img = (p < NS) ? desc1 : desc2;
    float py = g_pts[p*2 + 0];
    float px = g_pts[p*2 + 1];
    // xn = 2*px/511 - 1 ; ix = ((xn+1)*128 - 1)/2   (all separate rn ops)
    float xn = __fsub_rn(__fdiv_rn(__fmul_rn(2.0f, px), 511.0f), 1.0f);
    float yn = __fsub_rn(__fdiv_rn(__fmul_rn(2.0f, py), 511.0f), 1.0f);
    float ix = __fdiv_rn(__fsub_rn(__fmul_rn(__fadd_rn(xn, 1.0f), 128.0f), 1.0f), 2.0f);
    float iy = __fdiv_rn(__fsub_rn(__fmul_rn(__fadd_rn(yn, 1.0f), 128.0f), 1.0f), 2.0f);
    float x0f = floorf(ix), y0f = floorf(iy);
    float wx = __fsub_rn(ix, x0f), wy = __fsub_rn(iy, y0f);
    int x0 = (int)x0f, y0 = (int)y0f;
    int x1 = x0 + 1,  y1 = y0 + 1;

    float inb00 = ((x0 >= 0) & (x0 < HW) & (y0 >= 0) & (y0 < HW)) ? 1.0f : 0.0f;
    float inb10 = ((x1 >= 0) & (x1 < HW) & (y0 >= 0) & (y0 < HW)) ? 1.0f : 0.0f;
    float inb01 = ((x0 >= 0) & (x0 < HW) & (y1 >= 0) & (y1 < HW)) ? 1.0f : 0.0f;
    float inb11 = ((x1 >= 0) & (x1 < HW) & (y1 >= 0) & (y1 < HW)) ? 1.0f : 0.0f;
    int xc0 = min(max(x0, 0), HW-1), yc0 = min(max(y0, 0), HW-1);
    int xc1 = min(max(x1, 0), HW-1), yc1 = min(max(y1, 0), HW-1);

    // gather = img * inb (reference multiplies by the mask)
    float g00 = __fmul_rn(img[d*HW*HW + yc0*HW + xc0], inb00);
    float g10 = __fmul_rn(img[d*HW*HW + yc0*HW + xc1], inb10);
    float g01 = __fmul_rn(img[d*HW*HW + yc1*HW + xc0], inb01);
    float g11 = __fmul_rn(img[d*HW*HW + yc1*HW + xc1], inb11);

    float omx = __fsub_rn(1.0f, wx), omy = __fsub_rn(1.0f, wy);
    float w00 = __fmul_rn(omx, omy);
    float w10 = __fmul_rn(wx,  omy);
    float w01 = __fmul_rn(omx, wy);
    float w11 = __fmul_rn(wx,  wy);

    // v = g00*w00 + g10*w10 + g01*w01 + g11*w11 : left-assoc adds, NO FMA
    float m0 = __fmul_rn(g00, w00);
    float m1 = __fmul_rn(g10, w10);
    float m2 = __fmul_rn(g01, w01);
    float m3 = __fmul_rn(g11, w11);
    float v = __fadd_rn(__fadd_rn(__fadd_rn(m0, m1), m2), m3);

    // ---- norm: XLA column-reduction order over the 128 (major) axis ----
    // partial[t] = ((v[t]^2 + v[t+32]^2) + v[t+64]^2) + v[t+96]^2, t = 0..31
    // then shfl-down tree: offsets 16, 8, 4, 2, 1.
    __shared__ float sq[DD];
    __shared__ float s_nrm;
    sq[d] = __fmul_rn(v, v);
    __syncthreads();
    if (d < 32) {
        float partial = sq[d];
        partial = __fadd_rn(partial, sq[d + 32]);
        partial = __fadd_rn(partial, sq[d + 64]);
        partial = __fadd_rn(partial, sq[d + 96]);
        #pragma unroll
        for (int off = 16; off > 0; off >>= 1) {
            float o = __shfl_down_sync(0xffffffffu, partial, off);
            partial = __fadd_rn(partial, o);
        }
        if (d == 0) s_nrm = __fsqrt_rn(partial);
    }
    __syncthreads();
    g_desc[p*DD + d] = __fdiv_rn(v, s_nrm);
}

// ---------------- 3) fused line_scores GEMM ----------------
// Tile: 16x16 line pairs per CTA (80x80 samples), K=128 in two 64-chunks.
// One thread = one (i,j) line pair -> 25 dot accumulators -> reduce to score.
// Dots: explicit __fmaf_rn, single accumulator, ascending k (cublas sgemm order).
#define LPAD 66   // padded shared stride (floats)

__global__ void k_linescores() {
    __shared__ float As[80*LPAD];
    __shared__ float Bs[80*LPAD];
    __shared__ char  Av[80], Bv[80];

    int tid = threadIdx.x;
    int ti = tid >> 4, tj = tid & 15;
    int i0 = blockIdx.y * 16;     // line offset set1
    int j0 = blockIdx.x * 16;     // line offset set2

    if (tid < 80) {
        Av[tid] = (char)g_valid[i0*S + tid];
        Bv[tid] = (char)g_valid[NS + j0*S + tid];
    }

    float acc[S][S];
    #pragma unroll
    for (int x = 0; x < S; x++)
        #pragma unroll
        for (int y = 0; y < S; y++) acc[x][y] = 0.0f;

    const float* Ag = &g_desc[(i0*S)*DD];
    const float* Bg = &g_desc[(NS + j0*S)*DD];

    for (int kk = 0; kk < DD; kk += 64) {
        __syncthreads();
        for (int idx = tid; idx < 80*32; idx += 256) {
            int r = idx >> 5, c2 = idx & 31;
            *(float2*)&As[r*LPAD + c2*2] = *(const float2*)&Ag[r*DD + kk + c2*2];
            *(float2*)&Bs[r*LPAD + c2*2] = *(const float2*)&Bg[r*DD + kk + c2*2];
        }
        __syncthreads();
        const float* Ap = &As[(ti*S)*LPAD];
        const float* Bp = &Bs[(tj*S)*LPAD];
        #pragma unroll 8
        for (int k = 0; k < 64; k++) {
            float av[S], bv[S];
            #pragma unroll
            for (int r = 0; r < S; r++) { av[r] = Ap[r*LPAD + k]; bv[r] = Bp[r*LPAD + k]; }
            #pragma unroll
            for (int x = 0; x < S; x++)
                #pragma unroll
                for (int y = 0; y < S; y++) acc[x][y] = __fmaf_rn(av[x], bv[y], acc[x][y]);
        }
    }

    // epilogue: mask, max/mean reductions (XLA reduce: max init -inf, sums ascending)
    bool va[S], vb[S];
    #pragma unroll
    for (int r = 0; r < S; r++) { va[r] = Av[ti*S + r] != 0; vb[r] = Bv[tj*S + r] != 0; }

    float blk[S][S];
    #pragma unroll
    for (int a = 0; a < S; a++)
        #pragma unroll
        for (int b = 0; b < S; b++)
            blk[a][b] = (va[a] && vb[b]) ? acc[a][b] : -1.0f;

    float s1 = 0.0f, c1 = 0.0f, s2 = 0.0f, c2 = 0.0f;
    #pragma unroll
    for (int a = 0; a < S; a++) {
        float m = -INFINITY;
        #pragma unroll
        for (int b = 0; b < S; b++) m = fmaxf(m, blk[a][b]);
        if (m != -1.0f) { s1 = __fadd_rn(s1, m); c1 = __fadd_rn(c1, 1.0f); }
    }
    #pragma unroll
    for (int b = 0; b < S; b++) {
        float m = -INFINITY;
        #pragma unroll
        for (int a = 0; a < S; a++) m = fmaxf(m, blk[a][b]);
        if (m != -1.0f) { s2 = __fadd_rn(s2, m); c2 = __fadd_rn(c2, 1.0f); }
    }
    float ls1v = __fdiv_rn(s1, c1);
    float ls2v = __fdiv_rn(s2, c2);
    float ls = __fdiv_rn(__fadd_rn(ls1v, ls2v), 2.0f);
    g_ls[(i0 + ti)*NL + (j0 + tj)] = ls;
}

// ---------------- 4) top-K per row (dir0) / per column (dir1) ----------------
// Replicates stable-ascending argsort[-K:]: comparator lexicographic on (value, index),
// output kept in ascending order (slot 9 = best).
__global__ void k_topk() {
    int t = blockIdx.x * blockDim.x + threadIdx.x;
    if (t >= 2*NL) return;
    int dir = t / NL, row = t % NL;

    float bv[TOPK]; int bi[TOPK];
    #pragma unroll
    for (int s = 0; s < TOPK; s++) { bv[s] = -INFINITY; bi[s] = -1; }
    float th = -INFINITY; int thi = -1;

    for (int j = 0; j < NL; j++) {
        float v = dir ? g_ls[j*NL + row] : g_ls[row*NL + j];
        if (v > th || (v == th && j > thi)) {
            int pos = 0;
            while (pos < TOPK-1 &&
                   (v > bv[pos+1] || (v == bv[pos+1] && j > bi[pos+1]))) {
                bv[pos] = bv[pos+1]; bi[pos] = bi[pos+1]; pos++;
            }
            bv[pos] = v; bi[pos] = j;
            th = bv[0]; thi = bi[0];
        }
    }
    #pragma unroll
    for (int s = 0; s < TOPK; s++)
        g_topk[dir*NL*TOPK + row*TOPK + s] = bi[s];
}

// ---------------- 5) recompute 5x5 blocks for top-K, run NW, argmax ----------------
__device__ float nw5(const float* s, bool flip) {
    float prev[6] = {0,0,0,0,0,0};
    #pragma unroll
    for (int a = 0; a < S; a++) {
        float nr[6]; nr[0] = 0.0f;
        float left = 0.0f;
        #pragma unroll
        for (int b = 0; b < S; b++) {
            float sc = __fsub_rn(s[a*S + (flip ? (S-1-b) : b)], GAPP);
            float cur = fmaxf(fmaxf(left, prev[b+1]), __fadd_rn(prev[b], sc));
            nr[b+1] = cur; left = cur;
        }
        #pragma unroll
        for (int b = 0; b < 6; b++) prev[b] = nr[b];
    }
    return prev[5];
}

#define QPAD 129
__global__ void k_nw() {
    int row = blockIdx.x;
    int dir = blockIdx.y;
    int tid = threadIdx.x;

    __shared__ float q[S*QPAD];
    __shared__ float o[S*QPAD];
    __shared__ float sblk[S*S];
    __shared__ float nwv[2*TOPK];
    __shared__ char  qv[S], ov[S];

    int qs = dir ? (NS + row*S) : (row*S);
    const int* topk = &g_topk[dir*NL*TOPK + row*TOPK];

    for (int idx = tid; idx < S*DD; idx += blockDim.x) {
        int r = idx >> 7, c = idx & 127;
        q[r*QPAD + c] = g_desc[(qs + r)*DD + c];
    }
    if (tid < S) qv[tid] = (char)g_valid[qs + tid];

    for (int t = 0; t < TOPK; t++) {
        int l = topk[t];
        int os = dir ? (l*S) : (NS + l*S);
        __syncthreads();  // protect o (and q on t==0) before overwrite/use
        for (int idx = tid; idx < S*DD; idx += blockDim.x) {
            int r = idx >> 7, c = idx & 127;
            o[r*QPAD + c] = g_desc[(os + r)*DD + c];
        }
        if (tid < S) ov[tid] = (char)g_valid[os + tid];
        __syncthreads();

        if (tid < S*S) {
            int a = tid / S, b = tid % S;  // a indexes q, b indexes o
            float acc = 0.0f;
            // ascending k, single accumulator, FFMA — same bits as the GEMM
            for (int k = 0; k < DD; k++)
                acc = __fmaf_rn(q[a*QPAD + k], o[b*QPAD + k], acc);
            sblk[tid] = (qv[a] && ov[b]) ? acc : -1.0f;
        }
        __syncwarp();
        if (tid == 0) {
            // Index algebra: for BOTH directions the NW matrix is sblk as-is,
            // and the flipped variant flips the second index (columns).
            nwv[t]        = nw5(sblk, false);
            nwv[t + TOPK] = nw5(sblk, true);
        }
    }
    __syncthreads();
    if (tid == 0) {
        float best = -INFINITY; int bidx = 0;
        #pragma unroll
        for (int t = 0; t < 2*TOPK; t++) {
            if (nwv[t] > best) { best = nwv[t]; bidx = t; }  // first max
        }
        g_matches[dir*NL + row] = topk[bidx % TOPK];
        if (dir == 0) {
            for (int t = 0; t < 2*TOPK; t++) g_nwout[row*2*TOPK + t] = nwv[t];
        }
    }
}

// ---------------- 6) mutual check + write output ----------------
__global__ void k_final(float* __restrict__ out, int out_size) {
    int i = blockIdx.x * blockDim.x + threadIdx.x;
    if (i >= NL) return;
    int m1 = g_matches[i];
    int m2 = g_matches[NL + m1];
    int res = (m2 == i) ? m1 : -1;

    if (out_size >= NL + NL*2*TOPK) {
        out[i] = (float)res;
        for (int t = 0; t < 2*TOPK; t++)
            out[NL + i*2*TOPK + t] = g_nwout[i*2*TOPK + t];
    } else if (out_size == NL*2*TOPK) {
        for (int t = 0; t < 2*TOPK; t++)
            out[i*2*TOPK + t] = g_nwout[i*2*TOPK + t];
    } else {
        out[i] = (float)res;
    }
}

// ---------------- launch ----------------
extern "C" void kernel_launch(void* const* d_in, const int* in_sizes, int n_in,
                              void* d_out, int out_size) {
    (void)in_sizes; (void)n_in;
    const float* seg1  = (const float*)d_in[0];
    const float* seg2  = (const float*)d_in[1];
    const float* desc1 = (const float*)d_in[2];
    const float* desc2 = (const float*)d_in[3];

    k_points<<<(2*NL + 255)/256, 256>>>(seg1, seg2);
    k_sample<<<2*NS, DD>>>(desc1, desc2);
    k_linescores<<<dim3(NL/16, NL/16), 256>>>();
    k_topk<<<(2*NL + 127)/128, 128>>>();
    k_nw<<<dim3(NL, 2), 128>>>();
    k_final<<<(NL + 255)/256, 256>>>((float*)d_out, out_size);
}

// round 5
// speedup vs baseline: 1.4196x; 1.4196x over previous
#include <cuda_runtime.h>
#include <math.h>

#define NL 1200          // lines per set
#define S  5             // NUM_SAMPLES
#define NS (NL*S)        // 6000 samples per set
#define DD 128           // descriptor dim
#define HW 128           // feature map H=W
#define TOPK 10
#define GAPP 0.1f
#define NITER 38         // ceil(NL/32)

// ---------------- scratch (no allocs allowed) ----------------
__device__ float g_pts[2*NS*2];        // (y,x) per sample
__device__ int   g_valid[2*NS];
__device__ float g_desc[2*NS*DD];      // normalized descriptors, sample-major
__device__ float g_ls[NL*NL];          // line_scores (dir1)
__device__ float g_lsT[NL*NL];         // transposed copy (dir2, coalesced reads)
__device__ int   g_topk[2*NL*TOPK];
__device__ float g_nwout[NL*2*TOPK];   // nw for direction 1 (the returned one)
__device__ int   g_matches[2*NL];

// ---------------- 1) sample line points (XLA-exact: no FMA contraction) ----------------
__global__ void k_points(const float* __restrict__ seg1,
                         const float* __restrict__ seg2) {
    int l = blockIdx.x * blockDim.x + threadIdx.x;
    if (l >= 2*NL) return;
    const float* seg = (l < NL) ? (seg1 + l*4) : (seg2 + (l-NL)*4);
    float sy = seg[0], sx = seg[1], ey = seg[2], ex = seg[3];
    float dy = __fsub_rn(ey, sy), dx = __fsub_rn(ex, sx);
    float len = __fsqrt_rn(__fadd_rn(__fmul_rn(dy, dy), __fmul_rn(dx, dx)));
    float ns = floorf(__fdiv_rn(len, 8.0f));
    ns = fminf(fmaxf(ns, 2.0f), 5.0f);
    float den = __fsub_rn(ns, 1.0f);
    float ivy = __fdiv_rn(dy, den);
    float ivx = __fdiv_rn(dx, den);
    #pragma unroll
    for (int k = 0; k < S; k++) {
        bool v = ((float)k < ns);
        float py = __fadd_rn(sy, __fmul_rn((float)k, ivy));
        float px = __fadd_rn(sx, __fmul_rn((float)k, ivx));
        g_pts[(l*S + k)*2 + 0] = v ? py : 0.0f;
        g_pts[(l*S + k)*2 + 1] = v ? px : 0.0f;
        g_valid[l*S + k] = v ? 1 : 0;
    }
}

// ---------------- 2) bilinear descriptor sampling + L2 normalize (XLA-exact) ----------------
__global__ void k_sample(const float* __restrict__ desc1,
                         const float* __restrict__ desc2) {
    int p = blockIdx.x;              // 0..2*NS-1
    int d = threadIdx.x;             // 0..127
    const float* img = (p < NS) ? desc1 : desc2;
    float py = g_pts[p*2 + 0];
    float px = g_pts[p*2 + 1];
    float xn = __fsub_rn(__fdiv_rn(__fmul_rn(2.0f, px), 511.0f), 1.0f);
    float yn = __fsub_rn(__fdiv_rn(__fmul_rn(2.0f, py), 511.0f), 1.0f);
    float ix = __fdiv_rn(__fsub_rn(__fmul_rn(__fadd_rn(xn, 1.0f), 128.0f), 1.0f), 2.0f);
    float iy = __fdiv_rn(__fsub_rn(__fmul_rn(__fadd_rn(yn, 1.0f), 128.0f), 1.0f), 2.0f);
    float x0f = floorf(ix), y0f = floorf(iy);
    float wx = __fsub_rn(ix, x0f), wy = __fsub_rn(iy, y0f);
    int x0 = (int)x0f, y0 = (int)y0f;
    int x1 = x0 + 1,  y1 = y0 + 1;

    float inb00 = ((x0 >= 0) & (x0 < HW) & (y0 >= 0) & (y0 < HW)) ? 1.0f : 0.0f;
    float inb10 = ((x1 >= 0) & (x1 < HW) & (y0 >= 0) & (y0 < HW)) ? 1.0f : 0.0f;
    float inb01 = ((x0 >= 0) & (x0 < HW) & (y1 >= 0) & (y1 < HW)) ? 1.0f : 0.0f;
    float inb11 = ((x1 >= 0) & (x1 < HW) & (y1 >= 0) & (y1 < HW)) ? 1.0f : 0.0f;
    int xc0 = min(max(x0, 0), HW-1), yc0 = min(max(y0, 0), HW-1);
    int xc1 = min(max(x1, 0), HW-1), yc1 = min(max(y1, 0), HW-1);

    float g00 = __fmul_rn(img[d*HW*HW + yc0*HW + xc0], inb00);
    float g10 = __fmul_rn(img[d*HW*HW + yc0*HW + xc1], inb10);
    float g01 = __fmul_rn(img[d*HW*HW + yc1*HW + xc0], inb01);
    float g11 = __fmul_rn(img[d*HW*HW + yc1*HW + xc1], inb11);

    float omx = __fsub_rn(1.0f, wx), omy = __fsub_rn(1.0f, wy);
    float w00 = __fmul_rn(omx, omy);
    float w10 = __fmul_rn(wx,  omy);
    float w01 = __fmul_rn(omx, wy);
    float w11 = __fmul_rn(wx,  wy);

    float m0 = __fmul_rn(g00, w00);
    float m1 = __fmul_rn(g10, w10);
    float m2 = __fmul_rn(g01, w01);
    float m3 = __fmul_rn(g11, w11);
    float v = __fadd_rn(__fadd_rn(__fadd_rn(m0, m1), m2), m3);

    __shared__ float sq[DD];
    __shared__ float s_nrm;
    sq[d] = __fmul_rn(v, v);
    __syncthreads();
    if (d < 32) {
        float partial = sq[d];
        partial = __fadd_rn(partial, sq[d + 32]);
        partial = __fadd_rn(partial, sq[d + 64]);
        partial = __fadd_rn(partial, sq[d + 96]);
        #pragma unroll
        for (int off = 16; off > 0; off >>= 1) {
            float o = __shfl_down_sync(0xffffffffu, partial, off);
            partial = __fadd_rn(partial, o);
        }
        if (d == 0) s_nrm = __fsqrt_rn(partial);
    }
    __syncthreads();
    g_desc[p*DD + d] = __fdiv_rn(v, s_nrm);
}

// ---------------- 3) fused line_scores GEMM ----------------
#define LPAD 66   // padded shared stride (floats)

__global__ void k_linescores() {
    __shared__ float As[80*LPAD];
    __shared__ float Bs[80*LPAD];
    __shared__ char  Av[80], Bv[80];

    int tid = threadIdx.x;
    int ti = tid >> 4, tj = tid & 15;
    int i0 = blockIdx.y * 16;     // line offset set1
    int j0 = blockIdx.x * 16;     // line offset set2

    if (tid < 80) {
        Av[tid] = (char)g_valid[i0*S + tid];
        Bv[tid] = (char)g_valid[NS + j0*S + tid];
    }

    float acc[S][S];
    #pragma unroll
    for (int x = 0; x < S; x++)
        #pragma unroll
        for (int y = 0; y < S; y++) acc[x][y] = 0.0f;

    const float* Ag = &g_desc[(i0*S)*DD];
    const float* Bg = &g_desc[(NS + j0*S)*DD];

    for (int kk = 0; kk < DD; kk += 64) {
        __syncthreads();
        for (int idx = tid; idx < 80*32; idx += 256) {
            int r = idx >> 5, c2 = idx & 31;
            *(float2*)&As[r*LPAD + c2*2] = *(const float2*)&Ag[r*DD + kk + c2*2];
            *(float2*)&Bs[r*LPAD + c2*2] = *(const float2*)&Bg[r*DD + kk + c2*2];
        }
        __syncthreads();
        const float* Ap = &As[(ti*S)*LPAD];
        const float* Bp = &Bs[(tj*S)*LPAD];
        #pragma unroll 8
        for (int k = 0; k < 64; k++) {
            float av[S], bv[S];
            #pragma unroll
            for (int r = 0; r < S; r++) { av[r] = Ap[r*LPAD + k]; bv[r] = Bp[r*LPAD + k]; }
            #pragma unroll
            for (int x = 0; x < S; x++)
                #pragma unroll
                for (int y = 0; y < S; y++) acc[x][y] = __fmaf_rn(av[x], bv[y], acc[x][y]);
        }
    }

    bool va[S], vb[S];
    #pragma unroll
    for (int r = 0; r < S; r++) { va[r] = Av[ti*S + r] != 0; vb[r] = Bv[tj*S + r] != 0; }

    float blk[S][S];
    #pragma unroll
    for (int a = 0; a < S; a++)
        #pragma unroll
        for (int b = 0; b < S; b++)
            blk[a][b] = (va[a] && vb[b]) ? acc[a][b] : -1.0f;

    float s1 = 0.0f, c1 = 0.0f, s2 = 0.0f, c2 = 0.0f;
    #pragma unroll
    for (int a = 0; a < S; a++) {
        float m = -INFINITY;
        #pragma unroll
        for (int b = 0; b < S; b++) m = fmaxf(m, blk[a][b]);
        if (m != -1.0f) { s1 = __fadd_rn(s1, m); c1 = __fadd_rn(c1, 1.0f); }
    }
    #pragma unroll
    for (int b = 0; b < S; b++) {
        float m = -INFINITY;
        #pragma unroll
        for (int a = 0; a < S; a++) m = fmaxf(m, blk[a][b]);
        if (m != -1.0f) { s2 = __fadd_rn(s2, m); c2 = __fadd_rn(c2, 1.0f); }
    }
    float ls1v = __fdiv_rn(s1, c1);
    float ls2v = __fdiv_rn(s2, c2);
    float ls = __fdiv_rn(__fadd_rn(ls1v, ls2v), 2.0f);
    int gi = i0 + ti, gj = j0 + tj;
    g_ls [gi*NL + gj] = ls;
    g_lsT[gj*NL + gi] = ls;   // transposed copy for coalesced dir-1 top-K
}

// ---------------- 4) top-K: warp per row, 10 rounds of lex argmax ----------------
// Semantics identical to stable-ascending argsort[-K:]:
//   k-th pick = lexicographic max (value, index) among entries strictly less
//   (lex) than the previous pick. Slots written descending: slot 9 = best.
__global__ void k_topk() {
    int gwarp = (blockIdx.x * blockDim.x + threadIdx.x) >> 5;
    int lane  = threadIdx.x & 31;
    if (gwarp >= 2*NL) return;
    int dir = gwarp / NL, row = gwarp % NL;
    const float* src = dir ? &g_lsT[row*NL] : &g_ls[row*NL];

    // cache this lane's strided candidates in registers (static indexing only)
    float vals[NITER];
    #pragma unroll
    for (int i = 0; i < NITER; i++) {
        int j = lane + i*32;
        vals[i] = (j < NL) ? src[j] : -INFINITY;
    }

    float pv = INFINITY; int pj = 0x7fffffff;
    int* outp = &g_topk[dir*NL*TOPK + row*TOPK];

    for (int t = 0; t < TOPK; t++) {
        float bv = -INFINITY; int bj = -1;
        #pragma unroll
        for (int i = 0; i < NITER; i++) {
            int j = lane + i*32;
            float v = vals[i];
            bool elig = (v < pv) || (v == pv && j < pj);
            bool better = (v > bv) || (v == bv && j > bj);
            if (elig && better) { bv = v; bj = j; }
        }
        #pragma unroll
        for (int off = 16; off > 0; off >>= 1) {
            float ov = __shfl_down_sync(0xffffffffu, bv, off);
            int   oj = __shfl_down_sync(0xffffffffu, bj, off);
            if (ov > bv || (ov == bv && oj > bj)) { bv = ov; bj = oj; }
        }
        bv = __shfl_sync(0xffffffffu, bv, 0);
        bj = __shfl_sync(0xffffffffu, bj, 0);
        pv = bv; pj = bj;
        if (lane == 0) outp[TOPK - 1 - t] = bj;
    }
}

// ---------------- 5) recompute 5x5 blocks for top-K, run NW, argmax ----------------
__device__ float nw5(const float* s, bool flip) {
    float prev[6] = {0,0,0,0,0,0};
    #pragma unroll
    for (int a = 0; a < S; a++) {
        float nr[6]; nr[0] = 0.0f;
        float left = 0.0f;
        #pragma unroll
        for (int b = 0; b < S; b++) {
            float sc = __fsub_rn(s[a*S + (flip ? (S-1-b) : b)], GAPP);
            float cur = fmaxf(fmaxf(left, prev[b+1]), __fadd_rn(prev[b], sc));
            nr[b+1] = cur; left = cur;
        }
        #pragma unroll
        for (int b = 0; b < 6; b++) prev[b] = nr[b];
    }
    return prev[5];
}

#define QPAD 129
__global__ void k_nw() {
    int row = blockIdx.x;
    int dir = blockIdx.y;
    int tid = threadIdx.x;

    __shared__ float q[S*QPAD];
    __shared__ float o[S*QPAD];
    __shared__ float sblk[S*S];
    __shared__ float nwv[2*TOPK];
    __shared__ char  qv[S], ov[S];

    int qs = dir ? (NS + row*S) : (row*S);
    const int* topk = &g_topk[dir*NL*TOPK + row*TOPK];

    for (int idx = tid; idx < S*DD; idx += blockDim.x) {
        int r = idx >> 7, c = idx & 127;
        q[r*QPAD + c] = g_desc[(qs + r)*DD + c];
    }
    if (tid < S) qv[tid] = (char)g_valid[qs + tid];

    for (int t = 0; t < TOPK; t++) {
        int l = topk[t];
        int os = dir ? (l*S) : (NS + l*S);
        __syncthreads();  // protect o (and q on t==0) before overwrite/use
        for (int idx = tid; idx < S*DD; idx += blockDim.x) {
            int r = idx >> 7, c = idx & 127;
            o[r*QPAD + c] = g_desc[(os + r)*DD + c];
        }
        if (tid < S) ov[tid] = (char)g_valid[os + tid];
        __syncthreads();

        if (tid < S*S) {
            int a = tid / S, b = tid % S;  // a indexes q, b indexes o
            float acc = 0.0f;
            for (int k = 0; k < DD; k++)
                acc = __fmaf_rn(q[a*QPAD + k], o[b*QPAD + k], acc);
            sblk[tid] = (qv[a] && ov[b]) ? acc : -1.0f;
        }
        __syncwarp();
        if (tid == 0) {
            nwv[t]        = nw5(sblk, false);
            nwv[t + TOPK] = nw5(sblk, true);
        }
    }
    __syncthreads();
    if (tid == 0) {
        float best = -INFINITY; int bidx = 0;
        #pragma unroll
        for (int t = 0; t < 2*TOPK; t++) {
            if (nwv[t] > best) { best = nwv[t]; bidx = t; }  // first max
        }
        g_matches[dir*NL + row] = topk[bidx % TOPK];
        if (dir == 0) {
            for (int t = 0; t < 2*TOPK; t++) g_nwout[row*2*TOPK + t] = nwv[t];
        }
    }
}

// ---------------- 6) mutual check + write output ----------------
__global__ void k_final(float* __restrict__ out, int out_size) {
    int i = blockIdx.x * blockDim.x + threadIdx.x;
    if (i >= NL) return;
    int m1 = g_matches[i];
    int m2 = g_matches[NL + m1];
    int res = (m2 == i) ? m1 : -1;

    if (out_size >= NL + NL*2*TOPK) {
        out[i] = (float)res;
        for (int t = 0; t < 2*TOPK; t++)
            out[NL + i*2*TOPK + t] = g_nwout[i*2*TOPK + t];
    } else if (out_size == NL*2*TOPK) {
        for (int t = 0; t < 2*TOPK; t++)
            out[i*2*TOPK + t] = g_nwout[i*2*TOPK + t];
    } else {
        out[i] = (float)res;
    }
}

// ---------------- launch ----------------
extern "C" void kernel_launch(void* const* d_in, const int* in_sizes, int n_in,
                              void* d_out, int out_size) {
    (void)in_sizes; (void)n_in;
    const float* seg1  = (const float*)d_in[0];
    const float* seg2  = (const float*)d_in[1];
    const float* desc1 = (const float*)d_in[2];
    const float* desc2 = (const float*)d_in[3];

    k_points<<<(2*NL + 255)/256, 256>>>(seg1, seg2);
    k_sample<<<2*NS, DD>>>(desc1, desc2);
    k_linescores<<<dim3(NL/16, NL/16), 256>>>();
    k_topk<<<(2*NL*32 + 255)/256, 256>>>();   // warp per row
    k_nw<<<dim3(NL, 2), 128>>>();
    k_final<<<(NL + 255)/256, 256>>>((float*)d_out, out_size);
}

// round 6
// speedup vs baseline: 1.7490x; 1.2320x over previous
#include <cuda_runtime.h>
#include <math.h>

#define NL 1200          // lines per set
#define S  5             // NUM_SAMPLES
#define NS (NL*S)        // 6000 samples per set
#define DD 128           // descriptor dim
#define HW 128           // feature map H=W
#define TOPK 10
#define GAPP 0.1f
#define NITER 38         // ceil(NL/32)

// ---------------- scratch (no allocs allowed) ----------------
__device__ float g_pts[2*NS*2];
__device__ int   g_valid[2*NS];
__device__ float g_descT[2*HW*HW*DD];  // desc transposed to (p, d) per image
__device__ float g_desc[2*NS*DD];      // normalized descriptors, sample-major
__device__ float g_ls[NL*NL];          // line_scores (dir1)
__device__ float g_lsT[NL*NL];         // transposed copy (dir2)
__device__ int   g_topk[2*NL*TOPK];
__device__ float g_sblk[2*NL*TOPK*25]; // 5x5 blocks for NW
__device__ float g_nwout[NL*2*TOPK];
__device__ int   g_matches[2*NL];

// ---- f32x2 packed FMA helpers (each half = exact fp32 FMA) ----
__device__ __forceinline__ unsigned long long pack2(float lo, float hi) {
    unsigned long long r;
    asm("mov.b64 %0, {%1, %2};" : "=l"(r) : "f"(lo), "f"(hi));
    return r;
}
__device__ __forceinline__ float2 unpack2(unsigned long long v) {
    float2 f;
    asm("mov.b64 {%0, %1}, %2;" : "=f"(f.x), "=f"(f.y) : "l"(v));
    return f;
}
__device__ __forceinline__ void fma2(unsigned long long& acc,
                                     unsigned long long a, unsigned long long b) {
    asm("fma.rn.f32x2 %0, %1, %2, %0;" : "+l"(acc) : "l"(a), "l"(b));
}

// ---------------- 0) transpose desc (1,D,H,W) -> (H*W, D) ----------------
__global__ void k_transpose(const float* __restrict__ d1,
                            const float* __restrict__ d2) {
    __shared__ float tile[32][33];
    const float* in = blockIdx.z ? d2 : d1;
    float* out = g_descT + (size_t)blockIdx.z * (HW*HW*DD);
    int p0 = blockIdx.x * 32, d0 = blockIdx.y * 32;
    int tx = threadIdx.x, ty = threadIdx.y;   // 32 x 8
    #pragma unroll
    for (int j = 0; j < 32; j += 8)
        tile[ty + j][tx] = in[(d0 + ty + j)*(HW*HW) + p0 + tx];
    __syncthreads();
    #pragma unroll
    for (int j = 0; j < 32; j += 8)
        out[(p0 + ty + j)*DD + d0 + tx] = tile[tx][ty + j];
}

// ---------------- 1) sample line points (XLA-exact: no FMA contraction) ----------------
__global__ void k_points(const float* __restrict__ seg1,
                         const float* __restrict__ seg2) {
    int l = blockIdx.x * blockDim.x + threadIdx.x;
    if (l >= 2*NL) return;
    const float* seg = (l < NL) ? (seg1 + l*4) : (seg2 + (l-NL)*4);
    float sy = seg[0], sx = seg[1], ey = seg[2], ex = seg[3];
    float dy = __fsub_rn(ey, sy), dx = __fsub_rn(ex, sx);
    float len = __fsqrt_rn(__fadd_rn(__fmul_rn(dy, dy), __fmul_rn(dx, dx)));
    float ns = floorf(__fdiv_rn(len, 8.0f));
    ns = fminf(fmaxf(ns, 2.0f), 5.0f);
    float den = __fsub_rn(ns, 1.0f);
    float ivy = __fdiv_rn(dy, den);
    float ivx = __fdiv_rn(dx, den);
    #pragma unroll
    for (int k = 0; k < S; k++) {
        bool v = ((float)k < ns);
        float py = __fadd_rn(sy, __fmul_rn((float)k, ivy));
        float px = __fadd_rn(sx, __fmul_rn((float)k, ivx));
        g_pts[(l*S + k)*2 + 0] = v ? py : 0.0f;
        g_pts[(l*S + k)*2 + 1] = v ? px : 0.0f;
        g_valid[l*S + k] = v ? 1 : 0;
    }
}

// ---------------- 2) bilinear sampling + L2 normalize (XLA-exact, coalesced) ----------------
__global__ void k_sample() {
    int p = blockIdx.x;              // 0..2*NS-1
    int d = threadIdx.x;             // 0..127
    const float* img = g_descT + (size_t)((p < NS) ? 0 : 1) * (HW*HW*DD);
    float py = g_pts[p*2 + 0];
    float px = g_pts[p*2 + 1];
    float xn = __fsub_rn(__fdiv_rn(__fmul_rn(2.0f, px), 511.0f), 1.0f);
    float yn = __fsub_rn(__fdiv_rn(__fmul_rn(2.0f, py), 511.0f), 1.0f);
    float ix = __fdiv_rn(__fsub_rn(__fmul_rn(__fadd_rn(xn, 1.0f), 128.0f), 1.0f), 2.0f);
    float iy = __fdiv_rn(__fsub_rn(__fmul_rn(__fadd_rn(yn, 1.0f), 128.0f), 1.0f), 2.0f);
    float x0f = floorf(ix), y0f = floorf(iy);
    float wx = __fsub_rn(ix, x0f), wy = __fsub_rn(iy, y0f);
    int x0 = (int)x0f, y0 = (int)y0f;
    int x1 = x0 + 1,  y1 = y0 + 1;

    float inb00 = ((x0 >= 0) & (x0 < HW) & (y0 >= 0) & (y0 < HW)) ? 1.0f : 0.0f;
    float inb10 = ((x1 >= 0) & (x1 < HW) & (y0 >= 0) & (y0 < HW)) ? 1.0f : 0.0f;
    float inb01 = ((x0 >= 0) & (x0 < HW) & (y1 >= 0) & (y1 < HW)) ? 1.0f : 0.0f;
    float inb11 = ((x1 >= 0) & (x1 < HW) & (y1 >= 0) & (y1 < HW)) ? 1.0f : 0.0f;
    int xc0 = min(max(x0, 0), HW-1), yc0 = min(max(y0, 0), HW-1);
    int xc1 = min(max(x1, 0), HW-1), yc1 = min(max(y1, 0), HW-1);

    float g00 = __fmul_rn(img[(yc0*HW + xc0)*DD + d], inb00);
    float g10 = __fmul_rn(img[(yc0*HW + xc1)*DD + d], inb10);
    float g01 = __fmul_rn(img[(yc1*HW + xc0)*DD + d], inb01);
    float g11 = __fmul_rn(img[(yc1*HW + xc1)*DD + d], inb11);

    float omx = __fsub_rn(1.0f, wx), omy = __fsub_rn(1.0f, wy);
    float w00 = __fmul_rn(omx, omy);
    float w10 = __fmul_rn(wx,  omy);
    float w01 = __fmul_rn(omx, wy);
    float w11 = __fmul_rn(wx,  wy);

    float m0 = __fmul_rn(g00, w00);
    float m1 = __fmul_rn(g10, w10);
    float m2 = __fmul_rn(g01, w01);
    float m3 = __fmul_rn(g11, w11);
    float v = __fadd_rn(__fadd_rn(__fadd_rn(m0, m1), m2), m3);

    __shared__ float sq[DD];
    __shared__ float s_nrm;
    sq[d] = __fmul_rn(v, v);
    __syncthreads();
    if (d < 32) {
        float partial = sq[d];
        partial = __fadd_rn(partial, sq[d + 32]);
        partial = __fadd_rn(partial, sq[d + 64]);
        partial = __fadd_rn(partial, sq[d + 96]);
        #pragma unroll
        for (int off = 16; off > 0; off >>= 1) {
            float o = __shfl_down_sync(0xffffffffu, partial, off);
            partial = __fadd_rn(partial, o);
        }
        if (d == 0) s_nrm = __fsqrt_rn(partial);
    }
    __syncthreads();
    g_desc[p*DD + d] = __fdiv_rn(v, s_nrm);
}

// ---------------- 3) fused line_scores GEMM (f32x2-packed) ----------------
#define LPAD 68   // float4-aligned; B rows conflict-free per 8-lane phase

__global__ void k_linescores() {
    __shared__ float As[80*LPAD];
    __shared__ float Bs[80*LPAD];
    __shared__ char  Av[80], Bv[80];

    int tid = threadIdx.x;
    int ti = tid >> 4, tj = tid & 15;
    int i0 = blockIdx.y * 16;
    int j0 = blockIdx.x * 16;

    if (tid < 80) {
        Av[tid] = (char)g_valid[i0*S + tid];
        Bv[tid] = (char)g_valid[NS + j0*S + tid];
    }

    // packed accumulators: accp[x][0]=(b0,b1), accp[x][1]=(b2,b3);
    // accy4[0]=(x0,x1)@b4, accy4[1]=(x2,x3)@b4; acc44 scalar (x4,b4)
    unsigned long long accp[S][2], accy4[2];
    float acc44 = 0.0f;
    #pragma unroll
    for (int x = 0; x < S; x++) { accp[x][0] = 0ull; accp[x][1] = 0ull; }
    accy4[0] = 0ull; accy4[1] = 0ull;

    const float* Ag = &g_desc[(i0*S)*DD];
    const float* Bg = &g_desc[(NS + j0*S)*DD];

    for (int kk = 0; kk < DD; kk += 64) {
        __syncthreads();
        for (int idx = tid; idx < 80*16; idx += 256) {
            int r = idx >> 4, c4 = idx & 15;
            *(float4*)&As[r*LPAD + c4*4] = *(const float4*)&Ag[r*DD + kk + c4*4];
            *(float4*)&Bs[r*LPAD + c4*4] = *(const float4*)&Bg[r*DD + kk + c4*4];
        }
        __syncthreads();
        const float* Ap = &As[(ti*S)*LPAD];
        const float* Bp = &Bs[(tj*S)*LPAD];
        #pragma unroll
        for (int k = 0; k < 64; k += 4) {
            float4 a4[S], b4[S];
            #pragma unroll
            for (int r = 0; r < S; r++) {
                a4[r] = *(const float4*)&Ap[r*LPAD + k];
                b4[r] = *(const float4*)&Bp[r*LPAD + k];
            }
            #define SUBSTEP(COMP)                                              \
            {                                                                  \
                float av0=a4[0].COMP, av1=a4[1].COMP, av2=a4[2].COMP,          \
                      av3=a4[3].COMP, av4=a4[4].COMP;                          \
                float bv0=b4[0].COMP, bv1=b4[1].COMP, bv2=b4[2].COMP,          \
                      bv3=b4[3].COMP, bv4=b4[4].COMP;                          \
                unsigned long long b01 = pack2(bv0, bv1);                      \
                unsigned long long b23 = pack2(bv2, bv3);                      \
                unsigned long long aa;                                         \
                aa = pack2(av0, av0); fma2(accp[0][0], aa, b01); fma2(accp[0][1], aa, b23); \
                aa = pack2(av1, av1); fma2(accp[1][0], aa, b01); fma2(accp[1][1], aa, b23); \
                aa = pack2(av2, av2); fma2(accp[2][0], aa, b01); fma2(accp[2][1], aa, b23); \
                aa = pack2(av3, av3); fma2(accp[3][0], aa, b01); fma2(accp[3][1], aa, b23); \
                aa = pack2(av4, av4); fma2(accp[4][0], aa, b01); fma2(accp[4][1], aa, b23); \
                unsigned long long b44 = pack2(bv4, bv4);                      \
                fma2(accy4[0], pack2(av0, av1), b44);                          \
                fma2(accy4[1], pack2(av2, av3), b44);                          \
                acc44 = __fmaf_rn(av4, bv4, acc44);                            \
            }
            SUBSTEP(x) SUBSTEP(y) SUBSTEP(z) SUBSTEP(w)
            #undef SUBSTEP
        }
    }

    // unpack + mask + max/mean
    float acc[S][S];
    #pragma unroll
    for (int x = 0; x < S; x++) {
        float2 p01 = unpack2(accp[x][0]);
        float2 p23 = unpack2(accp[x][1]);
        acc[x][0] = p01.x; acc[x][1] = p01.y;
        acc[x][2] = p23.x; acc[x][3] = p23.y;
    }
    { float2 y0 = unpack2(accy4[0]); acc[0][4] = y0.x; acc[1][4] = y0.y; }
    { float2 y1 = unpack2(accy4[1]); acc[2][4] = y1.x; acc[3][4] = y1.y; }
    acc[4][4] = acc44;

    bool va[S], vb[S];
    #pragma unroll
    for (int r = 0; r < S; r++) { va[r] = Av[ti*S + r] != 0; vb[r] = Bv[tj*S + r] != 0; }

    float blk[S][S];
    #pragma unroll
    for (int a = 0; a < S; a++)
        #pragma unroll
        for (int b = 0; b < S; b++)
            blk[a][b] = (va[a] && vb[b]) ? acc[a][b] : -1.0f;

    float s1 = 0.0f, c1 = 0.0f, s2 = 0.0f, c2 = 0.0f;
    #pragma unroll
    for (int a = 0; a < S; a++) {
        float m = -INFINITY;
        #pragma unroll
        for (int b = 0; b < S; b++) m = fmaxf(m, blk[a][b]);
        if (m != -1.0f) { s1 = __fadd_rn(s1, m); c1 = __fadd_rn(c1, 1.0f); }
    }
    #pragma unroll
    for (int b = 0; b < S; b++) {
        float m = -INFINITY;
        #pragma unroll
        for (int a = 0; a < S; a++) m = fmaxf(m, blk[a][b]);
        if (m != -1.0f) { s2 = __fadd_rn(s2, m); c2 = __fadd_rn(c2, 1.0f); }
    }
    float ls = __fdiv_rn(__fadd_rn(__fdiv_rn(s1, c1), __fdiv_rn(s2, c2)), 2.0f);
    int gi = i0 + ti, gj = j0 + tj;
    g_ls [gi*NL + gj] = ls;
    g_lsT[gj*NL + gi] = ls;
}

// ---------------- 4) top-K: warp per row ----------------
__global__ void k_topk() {
    int gwarp = (blockIdx.x * blockDim.x + threadIdx.x) >> 5;
    int lane  = threadIdx.x & 31;
    if (gwarp >= 2*NL) return;
    int dir = gwarp / NL, row = gwarp % NL;
    const float* src = dir ? &g_lsT[row*NL] : &g_ls[row*NL];

    float vals[NITER];
    #pragma unroll
    for (int i = 0; i < NITER; i++) {
        int j = lane + i*32;
        vals[i] = (j < NL) ? src[j] : -INFINITY;
    }

    float pv = INFINITY; int pj = 0x7fffffff;
    int* outp = &g_topk[dir*NL*TOPK + row*TOPK];

    for (int t = 0; t < TOPK; t++) {
        float bv = -INFINITY; int bj = -1;
        #pragma unroll
        for (int i = 0; i < NITER; i++) {
            int j = lane + i*32;
            float v = vals[i];
            bool elig = (v < pv) || (v == pv && j < pj);
            bool better = (v > bv) || (v == bv && j > bj);
            if (elig && better) { bv = v; bj = j; }
        }
        #pragma unroll
        for (int off = 16; off > 0; off >>= 1) {
            float ov = __shfl_down_sync(0xffffffffu, bv, off);
            int   oj = __shfl_down_sync(0xffffffffu, bj, off);
            if (ov > bv || (ov == bv && oj > bj)) { bv = ov; bj = oj; }
        }
        bv = __shfl_sync(0xffffffffu, bv, 0);
        bj = __shfl_sync(0xffffffffu, bj, 0);
        pv = bv; pj = bj;
        if (lane == 0) outp[TOPK - 1 - t] = bj;
    }
}

// ---------------- 5a) recompute 5x5 blocks: warp per (dir,row,t) ----------------
__global__ void k_nwdots() {
    int w = (blockIdx.x * blockDim.x + threadIdx.x) >> 5;
    int lane = threadIdx.x & 31;
    if (w >= 2*NL*TOPK) return;
    int dir = w / (NL*TOPK);
    int rem = w % (NL*TOPK);
    int row = rem / TOPK, t = rem % TOPK;
    int l = g_topk[dir*NL*TOPK + row*TOPK + t];
    int qs = dir ? (NS + row*S) : (row*S);
    int os = dir ? (l*S) : (NS + l*S);
    if (lane < 25) {
        int a = lane / 5, b = lane % 5;
        const float* qp = &g_desc[(qs + a)*DD];
        const float* op = &g_desc[(os + b)*DD];
        float acc = 0.0f;
        #pragma unroll 8
        for (int k = 0; k < DD; k++)
            acc = __fmaf_rn(qp[k], op[k], acc);
        bool valid = g_valid[qs + a] && g_valid[os + b];
        g_sblk[w*25 + lane] = valid ? acc : -1.0f;
    }
}

// ---------------- 5b) NW DP + argmax: warp per (dir,row), lane per variant ----------------
__global__ void k_nwdp() {
    int gw = (blockIdx.x * blockDim.x + threadIdx.x) >> 5;
    int lane = threadIdx.x & 31;
    if (gw >= 2*NL) return;
    int dir = gw / NL, row = gw % NL;

    float nwv = -INFINITY;
    if (lane < 2*TOPK) {
        int tt = (lane < TOPK) ? lane : (lane - TOPK);
        bool flip = lane >= TOPK;
        const float* sb = &g_sblk[((dir*NL + row)*TOPK + tt)*25];
        float s[25];
        #pragma unroll
        for (int a = 0; a < 5; a++)
            #pragma unroll
            for (int b = 0; b < 5; b++)
                s[a*5 + b] = sb[a*5 + (flip ? (4 - b) : b)];

        float prev[6] = {0,0,0,0,0,0};
        #pragma unroll
        for (int a = 0; a < S; a++) {
            float nr[6]; nr[0] = 0.0f;
            float left = 0.0f;
            #pragma unroll
            for (int b = 0; b < S; b++) {
                float sc = __fsub_rn(s[a*5 + b], GAPP);
                float cur = fmaxf(fmaxf(left, prev[b+1]), __fadd_rn(prev[b], sc));
                nr[b+1] = cur; left = cur;
            }
            #pragma unroll
            for (int b = 0; b < 6; b++) prev[b] = nr[b];
        }
        nwv = prev[5];
    }

    // first-max over lanes 0..19 (ties -> lowest lane index)
    float bv = nwv; int bi = (lane < 2*TOPK) ? lane : (1 << 30);
    #pragma unroll
    for (int off = 16; off > 0; off >>= 1) {
        float ov = __shfl_down_sync(0xffffffffu, bv, off);
        int   oi = __shfl_down_sync(0xffffffffu, bi, off);
        if (ov > bv || (ov == bv && oi < bi)) { bv = ov; bi = oi; }
    }
    bi = __shfl_sync(0xffffffffu, bi, 0);
    if (lane == 0)
        g_matches[dir*NL + row] = g_topk[dir*NL*TOPK + row*TOPK + (bi % TOPK)];
    if (dir == 0 && lane < 2*TOPK)
        g_nwout[row*2*TOPK + lane] = nwv;
}

// ---------------- 6) mutual check + write output ----------------
__global__ void k_final(float* __restrict__ out, int out_size) {
    int i = blockIdx.x * blockDim.x + threadIdx.x;
    if (i >= NL) return;
    int m1 = g_matches[i];
    int m2 = g_matches[NL + m1];
    int res = (m2 == i) ? m1 : -1;

    if (out_size >= NL + NL*2*TOPK) {
        out[i] = (float)res;
        for (int t = 0; t < 2*TOPK; t++)
            out[NL + i*2*TOPK + t] = g_nwout[i*2*TOPK + t];
    } else if (out_size == NL*2*TOPK) {
        for (int t = 0; t < 2*TOPK; t++)
            out[i*2*TOPK + t] = g_nwout[i*2*TOPK + t];
    } else {
        out[i] = (float)res;
    }
}

// ---------------- launch ----------------
extern "C" void kernel_launch(void* const* d_in, const int* in_sizes, int n_in,
                              void* d_out, int out_size) {
    (void)in_sizes; (void)n_in;
    const float* seg1  = (const float*)d_in[0];
    const float* seg2  = (const float*)d_in[1];
    const float* desc1 = (const float*)d_in[2];
    const float* desc2 = (const float*)d_in[3];

    k_transpose<<<dim3(HW*HW/32, DD/32, 2), dim3(32, 8)>>>(desc1, desc2);
    k_points<<<(2*NL + 255)/256, 256>>>(seg1, seg2);
    k_sample<<<2*NS, DD>>>();
    k_linescores<<<dim3(NL/16, NL/16), 256>>>();
    k_topk<<<(2*NL*32 + 255)/256, 256>>>();
    k_nwdots<<<(2*NL*TOPK*32 + 255)/256, 256>>>();
    k_nwdp<<<(2*NL*32 + 255)/256, 256>>>();
    k_final<<<(NL + 255)/256, 256>>>((float*)d_out, out_size);
}

// round 7
// speedup vs baseline: 1.7911x; 1.0241x over previous
#include <cuda_runtime.h>
#include <math.h>

#define NL 1200          // lines per set
#define S  5             // NUM_SAMPLES
#define NS (NL*S)        // 6000 samples per set
#define DD 128           // descriptor dim
#define HW 128           // feature map H=W
#define TOPK 10
#define GAPP 0.1f
#define NITER 38         // ceil(NL/32)

typedef unsigned long long ull;

// ---------------- scratch (no allocs allowed) ----------------
__device__ float g_pts[2*NS*2];
__device__ int   g_valid[2*NS];
__device__ float g_descT[2*HW*HW*DD];  // desc transposed to (p, d) per image
__device__ float g_desc[2*NS*DD];      // normalized descriptors, sample-major
__device__ float g_ls[NL*NL];          // line_scores (dir1)
__device__ float g_lsT[NL*NL];         // transposed copy (dir2)
__device__ int   g_topk[2*NL*TOPK];
__device__ float g_sblk[2*NL*TOPK*25]; // 5x5 blocks for NW
__device__ float g_nwout[NL*2*TOPK];
__device__ int   g_matches[2*NL];

// ---- f32x2 packed FMA helpers (each half = exact fp32 FMA) ----
__device__ __forceinline__ ull pack2(float lo, float hi) {
    ull r;
    asm("mov.b64 %0, {%1, %2};" : "=l"(r) : "f"(lo), "f"(hi));
    return r;
}
__device__ __forceinline__ float2 unpack2(ull v) {
    float2 f;
    asm("mov.b64 {%0, %1}, %2;" : "=f"(f.x), "=f"(f.y) : "l"(v));
    return f;
}
__device__ __forceinline__ void fma2(ull& acc, ull a, ull b) {
    asm("fma.rn.f32x2 %0, %1, %2, %0;" : "+l"(acc) : "l"(a), "l"(b));
}
__device__ __forceinline__ unsigned smem_u32(const void* p) {
    unsigned r;
    asm("{ .reg .u64 t; cvta.to.shared.u64 t, %1; cvt.u32.u64 %0, t; }"
        : "=r"(r) : "l"(p));
    return r;
}
__device__ __forceinline__ ull lds64(unsigned a) {
    ull r;
    asm volatile("ld.shared.b64 %0, [%1];" : "=l"(r) : "r"(a));
    return r;
}
__device__ __forceinline__ float lds32(unsigned a) {
    float r;
    asm volatile("ld.shared.f32 %0, [%1];" : "=f"(r) : "r"(a));
    return r;
}

// ---------------- 0) transpose desc (1,D,H,W) -> (H*W, D) ----------------
__global__ void k_transpose(const float* __restrict__ d1,
                            const float* __restrict__ d2) {
    __shared__ float tile[32][33];
    const float* in = blockIdx.z ? d2 : d1;
    float* out = g_descT + (size_t)blockIdx.z * (HW*HW*DD);
    int p0 = blockIdx.x * 32, d0 = blockIdx.y * 32;
    int tx = threadIdx.x, ty = threadIdx.y;   // 32 x 8
    #pragma unroll
    for (int j = 0; j < 32; j += 8)
        tile[ty + j][tx] = in[(d0 + ty + j)*(HW*HW) + p0 + tx];
    __syncthreads();
    #pragma unroll
    for (int j = 0; j < 32; j += 8)
        out[(p0 + ty + j)*DD + d0 + tx] = tile[tx][ty + j];
}

// ---------------- 1) sample line points (XLA-exact: no FMA contraction) ----------------
__global__ void k_points(const float* __restrict__ seg1,
                         const float* __restrict__ seg2) {
    int l = blockIdx.x * blockDim.x + threadIdx.x;
    if (l >= 2*NL) return;
    const float* seg = (l < NL) ? (seg1 + l*4) : (seg2 + (l-NL)*4);
    float sy = seg[0], sx = seg[1], ey = seg[2], ex = seg[3];
    float dy = __fsub_rn(ey, sy), dx = __fsub_rn(ex, sx);
    float len = __fsqrt_rn(__fadd_rn(__fmul_rn(dy, dy), __fmul_rn(dx, dx)));
    float ns = floorf(__fdiv_rn(len, 8.0f));
    ns = fminf(fmaxf(ns, 2.0f), 5.0f);
    float den = __fsub_rn(ns, 1.0f);
    float ivy = __fdiv_rn(dy, den);
    float ivx = __fdiv_rn(dx, den);
    #pragma unroll
    for (int k = 0; k < S; k++) {
        bool v = ((float)k < ns);
        float py = __fadd_rn(sy, __fmul_rn((float)k, ivy));
        float px = __fadd_rn(sx, __fmul_rn((float)k, ivx));
        g_pts[(l*S + k)*2 + 0] = v ? py : 0.0f;
        g_pts[(l*S + k)*2 + 1] = v ? px : 0.0f;
        g_valid[l*S + k] = v ? 1 : 0;
    }
}

// ---------------- 2) bilinear sampling + L2 normalize (XLA-exact, coalesced) ----------------
__global__ void k_sample() {
    int p = blockIdx.x;              // 0..2*NS-1
    int d = threadIdx.x;             // 0..127
    const float* img = g_descT + (size_t)((p < NS) ? 0 : 1) * (HW*HW*DD);
    float py = g_pts[p*2 + 0];
    float px = g_pts[p*2 + 1];
    float xn = __fsub_rn(__fdiv_rn(__fmul_rn(2.0f, px), 511.0f), 1.0f);
    float yn = __fsub_rn(__fdiv_rn(__fmul_rn(2.0f, py), 511.0f), 1.0f);
    float ix = __fdiv_rn(__fsub_rn(__fmul_rn(__fadd_rn(xn, 1.0f), 128.0f), 1.0f), 2.0f);
    float iy = __fdiv_rn(__fsub_rn(__fmul_rn(__fadd_rn(yn, 1.0f), 128.0f), 1.0f), 2.0f);
    float x0f = floorf(ix), y0f = floorf(iy);
    float wx = __fsub_rn(ix, x0f), wy = __fsub_rn(iy, y0f);
    int x0 = (int)x0f, y0 = (int)y0f;
    int x1 = x0 + 1,  y1 = y0 + 1;

    float inb00 = ((x0 >= 0) & (x0 < HW) & (y0 >= 0) & (y0 < HW)) ? 1.0f : 0.0f;
    float inb10 = ((x1 >= 0) & (x1 < HW) & (y0 >= 0) & (y0 < HW)) ? 1.0f : 0.0f;
    float inb01 = ((x0 >= 0) & (x0 < HW) & (y1 >= 0) & (y1 < HW)) ? 1.0f : 0.0f;
    float inb11 = ((x1 >= 0) & (x1 < HW) & (y1 >= 0) & (y1 < HW)) ? 1.0f : 0.0f;
    int xc0 = min(max(x0, 0), HW-1), yc0 = min(max(y0, 0), HW-1);
    int xc1 = min(max(x1, 0), HW-1), yc1 = min(max(y1, 0), HW-1);

    float g00 = __fmul_rn(img[(yc0*HW + xc0)*DD + d], inb00);
    float g10 = __fmul_rn(img[(yc0*HW + xc1)*DD + d], inb10);
    float g01 = __fmul_rn(img[(yc1*HW + xc0)*DD + d], inb01);
    float g11 = __fmul_rn(img[(yc1*HW + xc1)*DD + d], inb11);

    float omx = __fsub_rn(1.0f, wx), omy = __fsub_rn(1.0f, wy);
    float w00 = __fmul_rn(omx, omy);
    float w10 = __fmul_rn(wx,  omy);
    float w01 = __fmul_rn(omx, wy);
    float w11 = __fmul_rn(wx,  wy);

    float m0 = __fmul_rn(g00, w00);
    float m1 = __fmul_rn(g10, w10);
    float m2 = __fmul_rn(g01, w01);
    float m3 = __fmul_rn(g11, w11);
    float v = __fadd_rn(__fadd_rn(__fadd_rn(m0, m1), m2), m3);

    __shared__ float sq[DD];
    __shared__ float s_nrm;
    sq[d] = __fmul_rn(v, v);
    __syncthreads();
    if (d < 32) {
        float partial = sq[d];
        partial = __fadd_rn(partial, sq[d + 32]);
        partial = __fadd_rn(partial, sq[d + 64]);
        partial = __fadd_rn(partial, sq[d + 96]);
        #pragma unroll
        for (int off = 16; off > 0; off >>= 1) {
            float o = __shfl_down_sync(0xffffffffu, partial, off);
            partial = __fadd_rn(partial, o);
        }
        if (d == 0) s_nrm = __fsqrt_rn(partial);
    }
    __syncthreads();
    g_desc[p*DD + d] = __fdiv_rn(v, s_nrm);
}

// ---------------- 3) fused line_scores GEMM (k-major smem, pair-from-memory) ----------------
// smem layout: As[k][96] — 16 lines x 6 slots (5 samples + pad), k-major.
// Line samples contiguous & 8B-aligned -> (s0,s1),(s2,s3) via single LDS.64.
#define KK  32      // k-chunk
#define AST 96      // slots per k row

__global__ void k_linescores() {
    __shared__ float As[KK*AST];
    __shared__ float Bs[KK*AST];
    __shared__ char  Av[80], Bv[80];

    int tid = threadIdx.x;
    int ti = tid >> 4, tj = tid & 15;
    int i0 = blockIdx.y * 16;
    int j0 = blockIdx.x * 16;

    if (tid < 80) {
        Av[tid] = (char)g_valid[i0*S + tid];
        Bv[tid] = (char)g_valid[NS + j0*S + tid];
    }

    // accM[x][q]: (dot(x,b0),dot(x,b1)) / (dot(x,b2),dot(x,b3))
    // accC[p]:    (dot(x0,b4),dot(x1,b4)) / (dot(x2,b4),dot(x3,b4)); acc44 = dot(x4,b4)
    ull accM[S][2], accC[2];
    float acc44 = 0.0f;
    #pragma unroll
    for (int x = 0; x < S; x++) { accM[x][0] = 0ull; accM[x][1] = 0ull; }
    accC[0] = 0ull; accC[1] = 0ull;

    const float* Ag = &g_desc[(i0*S)*DD];
    const float* Bg = &g_desc[(NS + j0*S)*DD];

    unsigned aBase = smem_u32(As) + (6*ti)*4;
    unsigned bBase = smem_u32(Bs) + (6*tj)*4;

    for (int kk = 0; kk < DD; kk += KK) {
        __syncthreads();
        // fill k-major tiles: 80 samples x 8 float4 each
        for (int idx = tid; idx < 80*8; idx += 256) {
            int r  = idx >> 3;          // sample 0..79
            int kq = (idx & 7) * 4;     // k offset in chunk
            int slot = (r/5)*6 + (r%5);
            float4 a = *(const float4*)&Ag[r*DD + kk + kq];
            float4 b = *(const float4*)&Bg[r*DD + kk + kq];
            As[(kq+0)*AST + slot] = a.x;
            As[(kq+1)*AST + slot] = a.y;
            As[(kq+2)*AST + slot] = a.z;
            As[(kq+3)*AST + slot] = a.w;
            Bs[(kq+0)*AST + slot] = b.x;
            Bs[(kq+1)*AST + slot] = b.y;
            Bs[(kq+2)*AST + slot] = b.z;
            Bs[(kq+3)*AST + slot] = b.w;
        }
        __syncthreads();

        #pragma unroll 8
        for (int k = 0; k < KK; k++) {
            unsigned ao = aBase + k*(AST*4);
            unsigned bo = bBase + k*(AST*4);
            float a0 = lds32(ao), a1 = lds32(ao+4), a2 = lds32(ao+8),
                  a3 = lds32(ao+12), a4 = lds32(ao+16);
            ull bp01 = lds64(bo);        // (b0,b1) straight from smem
            ull bp23 = lds64(bo+8);      // (b2,b3)
            float b4 = lds32(bo+16);

            ull ad0 = pack2(a0,a0), ad1 = pack2(a1,a1), ad2 = pack2(a2,a2),
                ad3 = pack2(a3,a3), ad4 = pack2(a4,a4);
            ull ap01 = pack2(a0,a1), ap23 = pack2(a2,a3);
            ull b4d  = pack2(b4,b4);

            fma2(accM[0][0], ad0, bp01); fma2(accM[0][1], ad0, bp23);
            fma2(accM[1][0], ad1, bp01); fma2(accM[1][1], ad1, bp23);
            fma2(accM[2][0], ad2, bp01); fma2(accM[2][1], ad2, bp23);
            fma2(accM[3][0], ad3, bp01); fma2(accM[3][1], ad3, bp23);
            fma2(accM[4][0], ad4, bp01); fma2(accM[4][1], ad4, bp23);
            fma2(accC[0], ap01, b4d);
            fma2(accC[1], ap23, b4d);
            acc44 = __fmaf_rn(a4, b4, acc44);
        }
    }

    // unpack
    float acc[S][S];
    #pragma unroll
    for (int x = 0; x < S; x++) {
        float2 p01 = unpack2(accM[x][0]);
        float2 p23 = unpack2(accM[x][1]);
        acc[x][0] = p01.x; acc[x][1] = p01.y;
        acc[x][2] = p23.x; acc[x][3] = p23.y;
    }
    { float2 c0 = unpack2(accC[0]); acc[0][4] = c0.x; acc[1][4] = c0.y; }
    { float2 c1 = unpack2(accC[1]); acc[2][4] = c1.x; acc[3][4] = c1.y; }
    acc[4][4] = acc44;

    bool va[S], vb[S];
    #pragma unroll
    for (int r = 0; r < S; r++) { va[r] = Av[ti*S + r] != 0; vb[r] = Bv[tj*S + r] != 0; }

    float blk[S][S];
    #pragma unroll
    for (int a = 0; a < S; a++)
        #pragma unroll
        for (int b = 0; b < S; b++)
            blk[a][b] = (va[a] && vb[b]) ? acc[a][b] : -1.0f;

    float s1 = 0.0f, c1 = 0.0f, s2 = 0.0f, c2 = 0.0f;
    #pragma unroll
    for (int a = 0; a < S; a++) {
        float m = -INFINITY;
        #pragma unroll
        for (int b = 0; b < S; b++) m = fmaxf(m, blk[a][b]);
        if (m != -1.0f) { s1 = __fadd_rn(s1, m); c1 = __fadd_rn(c1, 1.0f); }
    }
    #pragma unroll
    for (int b = 0; b < S; b++) {
        float m = -INFINITY;
        #pragma unroll
        for (int a = 0; a < S; a++) m = fmaxf(m, blk[a][b]);
        if (m != -1.0f) { s2 = __fadd_rn(s2, m); c2 = __fadd_rn(c2, 1.0f); }
    }
    float ls = __fdiv_rn(__fadd_rn(__fdiv_rn(s1, c1), __fdiv_rn(s2, c2)), 2.0f);
    int gi = i0 + ti, gj = j0 + tj;
    g_ls [gi*NL + gj] = ls;
    g_lsT[gj*NL + gi] = ls;
}

// ---------------- 4) top-K: warp per row ----------------
__global__ void k_topk() {
    int gwarp = (blockIdx.x * blockDim.x + threadIdx.x) >> 5;
    int lane  = threadIdx.x & 31;
    if (gwarp >= 2*NL) return;
    int dir = gwarp / NL, row = gwarp % NL;
    const float* src = dir ? &g_lsT[row*NL] : &g_ls[row*NL];

    float vals[NITER];
    #pragma unroll
    for (int i = 0; i < NITER; i++) {
        int j = lane + i*32;
        vals[i] = (j < NL) ? src[j] : -INFINITY;
    }

    float pv = INFINITY; int pj = 0x7fffffff;
    int* outp = &g_topk[dir*NL*TOPK + row*TOPK];

    for (int t = 0; t < TOPK; t++) {
        float bv = -INFINITY; int bj = -1;
        #pragma unroll
        for (int i = 0; i < NITER; i++) {
            int j = lane + i*32;
            float v = vals[i];
            bool elig = (v < pv) || (v == pv && j < pj);
            bool better = (v > bv) || (v == bv && j > bj);
            if (elig && better) { bv = v; bj = j; }
        }
        #pragma unroll
        for (int off = 16; off > 0; off >>= 1) {
            float ov = __shfl_down_sync(0xffffffffu, bv, off);
            int   oj = __shfl_down_sync(0xffffffffu, bj, off);
            if (ov > bv || (ov == bv && oj > bj)) { bv = ov; bj = oj; }
        }
        bv = __shfl_sync(0xffffffffu, bv, 0);
        bj = __shfl_sync(0xffffffffu, bj, 0);
        pv = bv; pj = bj;
        if (lane == 0) outp[TOPK - 1 - t] = bj;
    }
}

// ---------------- 5a) recompute 5x5 blocks: warp per (dir,row,t) ----------------
__global__ void k_nwdots() {
    int w = (blockIdx.x * blockDim.x + threadIdx.x) >> 5;
    int lane = threadIdx.x & 31;
    if (w >= 2*NL*TOPK) return;
    int dir = w / (NL*TOPK);
    int rem = w % (NL*TOPK);
    int row = rem / TOPK, t = rem % TOPK;
    int l = g_topk[dir*NL*TOPK + row*TOPK + t];
    int qs = dir ? (NS + row*S) : (row*S);
    int os = dir ? (l*S) : (NS + l*S);
    if (lane < 25) {
        int a = lane / 5, b = lane % 5;
        const float* qp = &g_desc[(qs + a)*DD];
        const float* op = &g_desc[(os + b)*DD];
        float acc = 0.0f;
        #pragma unroll 8
        for (int k = 0; k < DD; k++)
            acc = __fmaf_rn(qp[k], op[k], acc);
        bool valid = g_valid[qs + a] && g_valid[os + b];
        g_sblk[w*25 + lane] = valid ? acc : -1.0f;
    }
}

// ---------------- 5b) NW DP + argmax: warp per (dir,row), lane per variant ----------------
__global__ void k_nwdp() {
    int gw = (blockIdx.x * blockDim.x + threadIdx.x) >> 5;
    int lane = threadIdx.x & 31;
    if (gw >= 2*NL) return;
    int dir = gw / NL, row = gw % NL;

    float nwv = -INFINITY;
    if (lane < 2*TOPK) {
        int tt = (lane < TOPK) ? lane : (lane - TOPK);
        bool flip = lane >= TOPK;
        const float* sb = &g_sblk[((dir*NL + row)*TOPK + tt)*25];
        float s[25];
        #pragma unroll
        for (int a = 0; a < 5; a++)
            #pragma unroll
            for (int b = 0; b < 5; b++)
                s[a*5 + b] = sb[a*5 + (flip ? (4 - b) : b)];

        float prev[6] = {0,0,0,0,0,0};
        #pragma unroll
        for (int a = 0; a < S; a++) {
            float nr[6]; nr[0] = 0.0f;
            float left = 0.0f;
            #pragma unroll
            for (int b = 0; b < S; b++) {
                float sc = __fsub_rn(s[a*5 + b], GAPP);
                float cur = fmaxf(fmaxf(left, prev[b+1]), __fadd_rn(prev[b], sc));
                nr[b+1] = cur; left = cur;
            }
            #pragma unroll
            for (int b = 0; b < 6; b++) prev[b] = nr[b];
        }
        nwv = prev[5];
    }

    float bv = nwv; int bi = (lane < 2*TOPK) ? lane : (1 << 30);
    #pragma unroll
    for (int off = 16; off > 0; off >>= 1) {
        float ov = __shfl_down_sync(0xffffffffu, bv, off);
        int   oi = __shfl_down_sync(0xffffffffu, bi, off);
        if (ov > bv || (ov == bv && oi < bi)) { bv = ov; bi = oi; }
    }
    bi = __shfl_sync(0xffffffffu, bi, 0);
    if (lane == 0)
        g_matches[dir*NL + row] = g_topk[dir*NL*TOPK + row*TOPK + (bi % TOPK)];
    if (dir == 0 && lane < 2*TOPK)
        g_nwout[row*2*TOPK + lane] = nwv;
}

// ---------------- 6) mutual check + write output ----------------
__global__ void k_final(float* __restrict__ out, int out_size) {
    int i = blockIdx.x * blockDim.x + threadIdx.x;
    if (i >= NL) return;
    int m1 = g_matches[i];
    int m2 = g_matches[NL + m1];
    int res = (m2 == i) ? m1 : -1;

    if (out_size >= NL + NL*2*TOPK) {
        out[i] = (float)res;
        for (int t = 0; t < 2*TOPK; t++)
            out[NL + i*2*TOPK + t] = g_nwout[i*2*TOPK + t];
    } else if (out_size == NL*2*TOPK) {
        for (int t = 0; t < 2*TOPK; t++)
            out[i*2*TOPK + t] = g_nwout[i*2*TOPK + t];
    } else {
        out[i] = (float)res;
    }
}

// ---------------- launch ----------------
extern "C" void kernel_launch(void* const* d_in, const int* in_sizes, int n_in,
                              void* d_out, int out_size) {
    (void)in_sizes; (void)n_in;
    const float* seg1  = (const float*)d_in[0];
    const float* seg2  = (const float*)d_in[1];
    const float* desc1 = (const float*)d_in[2];
    const float* desc2 = (const float*)d_in[3];

    k_transpose<<<dim3(HW*HW/32, DD/32, 2), dim3(32, 8)>>>(desc1, desc2);
    k_points<<<(2*NL + 255)/256, 256>>>(seg1, seg2);
    k_sample<<<2*NS, DD>>>();
    k_linescores<<<dim3(NL/16, NL/16), 256>>>();
    k_topk<<<(2*NL*32 + 255)/256, 256>>>();
    k_nwdots<<<(2*NL*TOPK*32 + 255)/256, 256>>>();
    k_nwdp<<<(2*NL*32 + 255)/256, 256>>>();
    k_final<<<(NL + 255)/256, 256>>>((float*)d_out, out_size);
}

// round 8
// speedup vs baseline: 2.2501x; 1.2562x over previous
#include <cuda_runtime.h>
#include <math.h>

#define NL 1200          // lines per set
#define S  5             // NUM_SAMPLES
#define NS (NL*S)        // 6000 samples per set
#define DD 128           // descriptor dim
#define HW 128           // feature map H=W
#define TOPK 10
#define GAPP 0.1f
#define NITER 38         // ceil(NL/32)

typedef unsigned long long ull;

// ---------------- scratch (no allocs allowed) ----------------
__device__ float g_pts[2*NS*2];
__device__ int   g_valid[2*NS];
__device__ float g_descT[2*HW*HW*DD];  // desc transposed to (p, d) per image
__device__ float g_desc[2*NS*DD];      // normalized descriptors, sample-major
__device__ float g_ls[NL*NL];          // line_scores (dir1)
__device__ float g_lsT[NL*NL];         // transposed copy (dir2)
__device__ int   g_topk[2*NL*TOPK];
__device__ float g_sblk[2*NL*TOPK*25]; // 5x5 blocks for NW
__device__ float g_nwout[NL*2*TOPK];
__device__ int   g_matches[2*NL];

// ---- f32x2 packed FMA helpers (each half = exact fp32 FMA) ----
__device__ __forceinline__ ull pack2(float lo, float hi) {
    ull r;
    asm("mov.b64 %0, {%1, %2};" : "=l"(r) : "f"(lo), "f"(hi));
    return r;
}
__device__ __forceinline__ float2 unpack2(ull v) {
    float2 f;
    asm("mov.b64 {%0, %1}, %2;" : "=f"(f.x), "=f"(f.y) : "l"(v));
    return f;
}
__device__ __forceinline__ void fma2(ull& acc, ull a, ull b) {
    asm("fma.rn.f32x2 %0, %1, %2, %0;" : "+l"(acc) : "l"(a), "l"(b));
}
__device__ __forceinline__ unsigned smem_u32(const void* p) {
    unsigned r;
    asm("{ .reg .u64 t; cvta.to.shared.u64 t, %1; cvt.u32.u64 %0, t; }"
        : "=r"(r) : "l"(p));
    return r;
}
__device__ __forceinline__ ull lds64(unsigned a) {
    ull r;
    asm volatile("ld.shared.b64 %0, [%1];" : "=l"(r) : "r"(a));
    return r;
}
__device__ __forceinline__ float lds32(unsigned a) {
    float r;
    asm volatile("ld.shared.f32 %0, [%1];" : "=f"(r) : "r"(a));
    return r;
}

// ---------------- 0) transpose desc (1,D,H,W) -> (H*W, D) ----------------
__global__ void k_transpose(const float* __restrict__ d1,
                            const float* __restrict__ d2) {
    __shared__ float tile[32][33];
    const float* in = blockIdx.z ? d2 : d1;
    float* out = g_descT + (size_t)blockIdx.z * (HW*HW*DD);
    int p0 = blockIdx.x * 32, d0 = blockIdx.y * 32;
    int tx = threadIdx.x, ty = threadIdx.y;   // 32 x 8
    #pragma unroll
    for (int j = 0; j < 32; j += 8)
        tile[ty + j][tx] = in[(d0 + ty + j)*(HW*HW) + p0 + tx];
    __syncthreads();
    #pragma unroll
    for (int j = 0; j < 32; j += 8)
        out[(p0 + ty + j)*DD + d0 + tx] = tile[tx][ty + j];
}

// ---------------- 1) sample line points (XLA-exact: no FMA contraction) ----------------
__global__ void k_points(const float* __restrict__ seg1,
                         const float* __restrict__ seg2) {
    int l = blockIdx.x * blockDim.x + threadIdx.x;
    if (l >= 2*NL) return;
    const float* seg = (l < NL) ? (seg1 + l*4) : (seg2 + (l-NL)*4);
    float sy = seg[0], sx = seg[1], ey = seg[2], ex = seg[3];
    float dy = __fsub_rn(ey, sy), dx = __fsub_rn(ex, sx);
    float len = __fsqrt_rn(__fadd_rn(__fmul_rn(dy, dy), __fmul_rn(dx, dx)));
    float ns = floorf(__fdiv_rn(len, 8.0f));
    ns = fminf(fmaxf(ns, 2.0f), 5.0f);
    float den = __fsub_rn(ns, 1.0f);
    float ivy = __fdiv_rn(dy, den);
    float ivx = __fdiv_rn(dx, den);
    #pragma unroll
    for (int k = 0; k < S; k++) {
        bool v = ((float)k < ns);
        float py = __fadd_rn(sy, __fmul_rn((float)k, ivy));
        float px = __fadd_rn(sx, __fmul_rn((float)k, ivx));
        g_pts[(l*S + k)*2 + 0] = v ? py : 0.0f;
        g_pts[(l*S + k)*2 + 1] = v ? px : 0.0f;
        g_valid[l*S + k] = v ? 1 : 0;
    }
}

// ---------------- 2) bilinear sampling + L2 normalize (XLA-exact, coalesced) ----------------
__global__ void k_sample() {
    int p = blockIdx.x;              // 0..2*NS-1
    int d = threadIdx.x;             // 0..127
    const float* img = g_descT + (size_t)((p < NS) ? 0 : 1) * (HW*HW*DD);
    float py = g_pts[p*2 + 0];
    float px = g_pts[p*2 + 1];
    float xn = __fsub_rn(__fdiv_rn(__fmul_rn(2.0f, px), 511.0f), 1.0f);
    float yn = __fsub_rn(__fdiv_rn(__fmul_rn(2.0f, py), 511.0f), 1.0f);
    float ix = __fdiv_rn(__fsub_rn(__fmul_rn(__fadd_rn(xn, 1.0f), 128.0f), 1.0f), 2.0f);
    float iy = __fdiv_rn(__fsub_rn(__fmul_rn(__fadd_rn(yn, 1.0f), 128.0f), 1.0f), 2.0f);
    float x0f = floorf(ix), y0f = floorf(iy);
    float wx = __fsub_rn(ix, x0f), wy = __fsub_rn(iy, y0f);
    int x0 = (int)x0f, y0 = (int)y0f;
    int x1 = x0 + 1,  y1 = y0 + 1;

    float inb00 = ((x0 >= 0) & (x0 < HW) & (y0 >= 0) & (y0 < HW)) ? 1.0f : 0.0f;
    float inb10 = ((x1 >= 0) & (x1 < HW) & (y0 >= 0) & (y0 < HW)) ? 1.0f : 0.0f;
    float inb01 = ((x0 >= 0) & (x0 < HW) & (y1 >= 0) & (y1 < HW)) ? 1.0f : 0.0f;
    float inb11 = ((x1 >= 0) & (x1 < HW) & (y1 >= 0) & (y1 < HW)) ? 1.0f : 0.0f;
    int xc0 = min(max(x0, 0), HW-1), yc0 = min(max(y0, 0), HW-1);
    int xc1 = min(max(x1, 0), HW-1), yc1 = min(max(y1, 0), HW-1);

    float g00 = __fmul_rn(img[(yc0*HW + xc0)*DD + d], inb00);
    float g10 = __fmul_rn(img[(yc0*HW + xc1)*DD + d], inb10);
    float g01 = __fmul_rn(img[(yc1*HW + xc0)*DD + d], inb01);
    float g11 = __fmul_rn(img[(yc1*HW + xc1)*DD + d], inb11);

    float omx = __fsub_rn(1.0f, wx), omy = __fsub_rn(1.0f, wy);
    float w00 = __fmul_rn(omx, omy);
    float w10 = __fmul_rn(wx,  omy);
    float w01 = __fmul_rn(omx, wy);
    float w11 = __fmul_rn(wx,  wy);

    float m0 = __fmul_rn(g00, w00);
    float m1 = __fmul_rn(g10, w10);
    float m2 = __fmul_rn(g01, w01);
    float m3 = __fmul_rn(g11, w11);
    float v = __fadd_rn(__fadd_rn(__fadd_rn(m0, m1), m2), m3);

    __shared__ float sq[DD];
    __shared__ float s_nrm;
    sq[d] = __fmul_rn(v, v);
    __syncthreads();
    if (d < 32) {
        float partial = sq[d];
        partial = __fadd_rn(partial, sq[d + 32]);
        partial = __fadd_rn(partial, sq[d + 64]);
        partial = __fadd_rn(partial, sq[d + 96]);
        #pragma unroll
        for (int off = 16; off > 0; off >>= 1) {
            float o = __shfl_down_sync(0xffffffffu, partial, off);
            partial = __fadd_rn(partial, o);
        }
        if (d == 0) s_nrm = __fsqrt_rn(partial);
    }
    __syncthreads();
    g_desc[p*DD + d] = __fdiv_rn(v, s_nrm);
}

// ---------------- 3) fused line_scores GEMM ----------------
// k-major smem, 2 j-lines per thread. 128 threads: ti=tid>>3 (16 i-lines),
// tjq=tid&7 (8 j-pairs -> 16 j-lines). AST=98: even (LDS.64 aligned),
// not 0 mod 32 (fill STS spread across banks).
#define KK  32
#define AST 98

__global__ void k_linescores() {
    __shared__ float As[KK*AST];
    __shared__ float Bs[KK*AST];
    __shared__ char  Av[80], Bv[80];

    int tid = threadIdx.x;           // 0..127
    int ti  = tid >> 3;              // 0..15
    int tjq = tid & 7;               // 0..7 (j-pair)
    int i0 = blockIdx.y * 16;
    int j0 = blockIdx.x * 16;

    if (tid < 80) {
        Av[tid] = (char)g_valid[i0*S + tid];
        Bv[tid] = (char)g_valid[NS + j0*S + tid];
    }

    // per j-line accumulators
    ull accM[2][S][2], accC[2][2];
    float acc44[2];
    #pragma unroll
    for (int jl = 0; jl < 2; jl++) {
        #pragma unroll
        for (int x = 0; x < S; x++) { accM[jl][x][0] = 0ull; accM[jl][x][1] = 0ull; }
        accC[jl][0] = 0ull; accC[jl][1] = 0ull;
        acc44[jl] = 0.0f;
    }

    const float* Ag = &g_desc[(i0*S)*DD];
    const float* Bg = &g_desc[(NS + j0*S)*DD];

    unsigned aBase = smem_u32(As) + (6*ti)*4;
    unsigned bBase = smem_u32(Bs) + (6*(2*tjq))*4;

    for (int kk = 0; kk < DD; kk += KK) {
        __syncthreads();
        // fill k-major tiles: 80 samples x 8 float4 each
        for (int idx = tid; idx < 80*8; idx += 128) {
            int r  = idx >> 3;          // sample 0..79
            int kq = (idx & 7) * 4;     // k offset in chunk
            int slot = (r/5)*6 + (r%5);
            float4 a = *(const float4*)&Ag[r*DD + kk + kq];
            float4 b = *(const float4*)&Bg[r*DD + kk + kq];
            As[(kq+0)*AST + slot] = a.x;
            As[(kq+1)*AST + slot] = a.y;
            As[(kq+2)*AST + slot] = a.z;
            As[(kq+3)*AST + slot] = a.w;
            Bs[(kq+0)*AST + slot] = b.x;
            Bs[(kq+1)*AST + slot] = b.y;
            Bs[(kq+2)*AST + slot] = b.z;
            Bs[(kq+3)*AST + slot] = b.w;
        }
        __syncthreads();

        #pragma unroll 8
        for (int k = 0; k < KK; k++) {
            unsigned ao = aBase + k*(AST*4);
            unsigned bo = bBase + k*(AST*4);
            float a0 = lds32(ao), a1 = lds32(ao+4), a2 = lds32(ao+8),
                  a3 = lds32(ao+12), a4 = lds32(ao+16);
            ull ad0 = pack2(a0,a0), ad1 = pack2(a1,a1), ad2 = pack2(a2,a2),
                ad3 = pack2(a3,a3), ad4 = pack2(a4,a4);
            ull ap01 = pack2(a0,a1), ap23 = pack2(a2,a3);

            #pragma unroll
            for (int jl = 0; jl < 2; jl++) {
                unsigned bj = bo + jl*24;
                ull bp01 = lds64(bj);
                ull bp23 = lds64(bj+8);
                float b4 = lds32(bj+16);
                ull b4d = pack2(b4,b4);

                fma2(accM[jl][0][0], ad0, bp01); fma2(accM[jl][0][1], ad0, bp23);
                fma2(accM[jl][1][0], ad1, bp01); fma2(accM[jl][1][1], ad1, bp23);
                fma2(accM[jl][2][0], ad2, bp01); fma2(accM[jl][2][1], ad2, bp23);
                fma2(accM[jl][3][0], ad3, bp01); fma2(accM[jl][3][1], ad3, bp23);
                fma2(accM[jl][4][0], ad4, bp01); fma2(accM[jl][4][1], ad4, bp23);
                fma2(accC[jl][0], ap01, b4d);
                fma2(accC[jl][1], ap23, b4d);
                acc44[jl] = __fmaf_rn(a4, b4, acc44[jl]);
            }
        }
    }

    bool va[S];
    #pragma unroll
    for (int r = 0; r < S; r++) va[r] = Av[ti*S + r] != 0;

    #pragma unroll
    for (int jl = 0; jl < 2; jl++) {
        int jloc = 2*tjq + jl;
        float acc[S][S];
        #pragma unroll
        for (int x = 0; x < S; x++) {
            float2 p01 = unpack2(accM[jl][x][0]);
            float2 p23 = unpack2(accM[jl][x][1]);
            acc[x][0] = p01.x; acc[x][1] = p01.y;
            acc[x][2] = p23.x; acc[x][3] = p23.y;
        }
        { float2 c0 = unpack2(accC[jl][0]); acc[0][4] = c0.x; acc[1][4] = c0.y; }
        { float2 c1 = unpack2(accC[jl][1]); acc[2][4] = c1.x; acc[3][4] = c1.y; }
        acc[4][4] = acc44[jl];

        bool vb[S];
        #pragma unroll
        for (int r = 0; r < S; r++) vb[r] = Bv[jloc*S + r] != 0;

        float blk[S][S];
        #pragma unroll
        for (int a = 0; a < S; a++)
            #pragma unroll
            for (int b = 0; b < S; b++)
                blk[a][b] = (va[a] && vb[b]) ? acc[a][b] : -1.0f;

        float s1 = 0.0f, c1 = 0.0f, s2 = 0.0f, c2 = 0.0f;
        #pragma unroll
        for (int a = 0; a < S; a++) {
            float m = -INFINITY;
            #pragma unroll
            for (int b = 0; b < S; b++) m = fmaxf(m, blk[a][b]);
            if (m != -1.0f) { s1 = __fadd_rn(s1, m); c1 = __fadd_rn(c1, 1.0f); }
        }
        #pragma unroll
        for (int b = 0; b < S; b++) {
            float m = -INFINITY;
            #pragma unroll
            for (int a = 0; a < S; a++) m = fmaxf(m, blk[a][b]);
            if (m != -1.0f) { s2 = __fadd_rn(s2, m); c2 = __fadd_rn(c2, 1.0f); }
        }
        float ls = __fdiv_rn(__fadd_rn(__fdiv_rn(s1, c1), __fdiv_rn(s2, c2)), 2.0f);
        int gi = i0 + ti, gj = j0 + jloc;
        g_ls [gi*NL + gj] = ls;
        g_lsT[gj*NL + gi] = ls;
    }
}

// ---------------- 4) top-K: warp per row ----------------
__global__ void k_topk() {
    int gwarp = (blockIdx.x * blockDim.x + threadIdx.x) >> 5;
    int lane  = threadIdx.x & 31;
    if (gwarp >= 2*NL) return;
    int dir = gwarp / NL, row = gwarp % NL;
    const float* src = dir ? &g_lsT[row*NL] : &g_ls[row*NL];

    float vals[NITER];
    #pragma unroll
    for (int i = 0; i < NITER; i++) {
        int j = lane + i*32;
        vals[i] = (j < NL) ? src[j] : -INFINITY;
    }

    float pv = INFINITY; int pj = 0x7fffffff;
    int* outp = &g_topk[dir*NL*TOPK + row*TOPK];

    for (int t = 0; t < TOPK; t++) {
        float bv = -INFINITY; int bj = -1;
        #pragma unroll
        for (int i = 0; i < NITER; i++) {
            int j = lane + i*32;
            float v = vals[i];
            bool elig = (v < pv) || (v == pv && j < pj);
            bool better = (v > bv) || (v == bv && j > bj);
            if (elig && better) { bv = v; bj = j; }
        }
        #pragma unroll
        for (int off = 16; off > 0; off >>= 1) {
            float ov = __shfl_down_sync(0xffffffffu, bv, off);
            int   oj = __shfl_down_sync(0xffffffffu, bj, off);
            if (ov > bv || (ov == bv && oj > bj)) { bv = ov; bj = oj; }
        }
        bv = __shfl_sync(0xffffffffu, bv, 0);
        bj = __shfl_sync(0xffffffffu, bj, 0);
        pv = bv; pj = bj;
        if (lane == 0) outp[TOPK - 1 - t] = bj;
    }
}

// ---------------- 5a) recompute 5x5 blocks: warp per (dir,row,t) ----------------
__global__ void k_nwdots() {
    int w = (blockIdx.x * blockDim.x + threadIdx.x) >> 5;
    int lane = threadIdx.x & 31;
    if (w >= 2*NL*TOPK) return;
    int dir = w / (NL*TOPK);
    int rem = w % (NL*TOPK);
    int row = rem / TOPK, t = rem % TOPK;
    int l = g_topk[dir*NL*TOPK + row*TOPK + t];
    int qs = dir ? (NS + row*S) : (row*S);
    int os = dir ? (l*S) : (NS + l*S);
    if (lane < 25) {
        int a = lane / 5, b = lane % 5;
        const float* qp = &g_desc[(qs + a)*DD];
        const float* op = &g_desc[(os + b)*DD];
        float acc = 0.0f;
        #pragma unroll 8
        for (int k = 0; k < DD; k++)
            acc = __fmaf_rn(qp[k], op[k], acc);
        bool valid = g_valid[qs + a] && g_valid[os + b];
        g_sblk[w*25 + lane] = valid ? acc : -1.0f;
    }
}

// ---------------- 5b) NW DP + argmax: warp per (dir,row), lane per variant ----------------
__global__ void k_nwdp() {
    int gw = (blockIdx.x * blockDim.x + threadIdx.x) >> 5;
    int lane = threadIdx.x & 31;
    if (gw >= 2*NL) return;
    int dir = gw / NL, row = gw % NL;

    float nwv = -INFINITY;
    if (lane < 2*TOPK) {
        int tt = (lane < TOPK) ? lane : (lane - TOPK);
        bool flip = lane >= TOPK;
        const float* sb = &g_sblk[((dir*NL + row)*TOPK + tt)*25];
        float s[25];
        #pragma unroll
        for (int a = 0; a < 5; a++)
            #pragma unroll
            for (int b = 0; b < 5; b++)
                s[a*5 + b] = sb[a*5 + (flip ? (4 - b) : b)];

        float prev[6] = {0,0,0,0,0,0};
        #pragma unroll
        for (int a = 0; a < S; a++) {
            float nr[6]; nr[0] = 0.0f;
            float left = 0.0f;
            #pragma unroll
            for (int b = 0; b < S; b++) {
                float sc = __fsub_rn(s[a*5 + b], GAPP);
                float cur = fmaxf(fmaxf(left, prev[b+1]), __fadd_rn(prev[b], sc));
                nr[b+1] = cur; left = cur;
            }
            #pragma unroll
            for (int b = 0; b < 6; b++) prev[b] = nr[b];
        }
        nwv = prev[5];
    }

    float bv = nwv; int bi = (lane < 2*TOPK) ? lane : (1 << 30);
    #pragma unroll
    for (int off = 16; off > 0; off >>= 1) {
        float ov = __shfl_down_sync(0xffffffffu, bv, off);
        int   oi = __shfl_down_sync(0xffffffffu, bi, off);
        if (ov > bv || (ov == bv && oi < bi)) { bv = ov; bi = oi; }
    }
    bi = __shfl_sync(0xffffffffu, bi, 0);
    if (lane == 0)
        g_matches[dir*NL + row] = g_topk[dir*NL*TOPK + row*TOPK + (bi % TOPK)];
    if (dir == 0 && lane < 2*TOPK)
        g_nwout[row*2*TOPK + lane] = nwv;
}

// ---------------- 6) mutual check + write output ----------------
__global__ void k_final(float* __restrict__ out, int out_size) {
    int i = blockIdx.x * blockDim.x + threadIdx.x;
    if (i >= NL) return;
    int m1 = g_matches[i];
    int m2 = g_matches[NL + m1];
    int res = (m2 == i) ? m1 : -1;

    if (out_size >= NL + NL*2*TOPK) {
        out[i] = (float)res;
        for (int t = 0; t < 2*TOPK; t++)
            out[NL + i*2*TOPK + t] = g_nwout[i*2*TOPK + t];
    } else if (out_size == NL*2*TOPK) {
        for (int t = 0; t < 2*TOPK; t++)
            out[i*2*TOPK + t] = g_nwout[i*2*TOPK + t];
    } else {
        out[i] = (float)res;
    }
}

// ---------------- launch ----------------
extern "C" void kernel_launch(void* const* d_in, const int* in_sizes, int n_in,
                              void* d_out, int out_size) {
    (void)in_sizes; (void)n_in;
    const float* seg1  = (const float*)d_in[0];
    const float* seg2  = (const float*)d_in[1];
    const float* desc1 = (const float*)d_in[2];
    const float* desc2 = (const float*)d_in[3];

    k_transpose<<<dim3(HW*HW/32, DD/32, 2), dim3(32, 8)>>>(desc1, desc2);
    k_points<<<(2*NL + 255)/256, 256>>>(seg1, seg2);
    k_sample<<<2*NS, DD>>>();
    k_linescores<<<dim3(NL/16, NL/16), 128>>>();
    k_topk<<<(2*NL*32 + 255)/256, 256>>>();
    k_nwdots<<<(2*NL*TOPK*32 + 255)/256, 256>>>();
    k_nwdp<<<(2*NL*32 + 255)/256, 256>>>();
    k_final<<<(NL + 255)/256, 256>>>((float*)d_out, out_size);
}

// round 9
// speedup vs baseline: 2.6018x; 1.1563x over previous
#include <cuda_runtime.h>
#include <math.h>

#define NL 1200          // lines per set
#define S  5             // NUM_SAMPLES
#define NS (NL*S)        // 6000 samples per set
#define DD 128           // descriptor dim
#define HW 128           // feature map H=W
#define TOPK 10
#define GAPP 0.1f
#define NITER 38         // ceil(NL/32)
#define CW   (NL*6)      // 7200: k-major row width (6 slots per line)

typedef unsigned long long ull;

// ---------------- scratch (no allocs allowed) ----------------
__device__ float g_pts[2*NS*2];
__device__ int   g_valid[2*NS];
__device__ float g_descT[2*HW*HW*DD];  // desc transposed to (p, d) per image
__device__ float g_desc[2*NS*DD];      // normalized descriptors, sample-major
__device__ float g_desck[2][DD][CW];   // k-major, slot-padded (line*6+s)
__device__ float g_ls[NL*NL];          // line_scores (dir1)
__device__ float g_lsT[NL*NL];         // transposed copy (dir2)
__device__ int   g_topk[2*NL*TOPK];
__device__ float g_sblk[2*NL*TOPK*25]; // 5x5 blocks for NW
__device__ float g_nwout[NL*2*TOPK];
__device__ int   g_matches[2*NL];

// ---- f32x2 packed FMA helpers (each half = exact fp32 FMA) ----
__device__ __forceinline__ ull pack2(float lo, float hi) {
    ull r;
    asm("mov.b64 %0, {%1, %2};" : "=l"(r) : "f"(lo), "f"(hi));
    return r;
}
__device__ __forceinline__ float2 unpack2(ull v) {
    float2 f;
    asm("mov.b64 {%0, %1}, %2;" : "=f"(f.x), "=f"(f.y) : "l"(v));
    return f;
}
__device__ __forceinline__ void fma2(ull& acc, ull a, ull b) {
    asm("fma.rn.f32x2 %0, %1, %2, %0;" : "+l"(acc) : "l"(a), "l"(b));
}
__device__ __forceinline__ unsigned smem_u32(const void* p) {
    unsigned r;
    asm("{ .reg .u64 t; cvta.to.shared.u64 t, %1; cvt.u32.u64 %0, t; }"
        : "=r"(r) : "l"(p));
    return r;
}
__device__ __forceinline__ ull lds64(unsigned a) {
    ull r;
    asm volatile("ld.shared.b64 %0, [%1];" : "=l"(r) : "r"(a));
    return r;
}
__device__ __forceinline__ float lds32(unsigned a) {
    float r;
    asm volatile("ld.shared.f32 %0, [%1];" : "=f"(r) : "r"(a));
    return r;
}
__device__ __forceinline__ void cpasync16(unsigned s, const void* g) {
    asm volatile("cp.async.ca.shared.global [%0], [%1], 16;" :: "r"(s), "l"(g));
}
__device__ __forceinline__ void cpcommit() {
    asm volatile("cp.async.commit_group;");
}
template <int N>
__device__ __forceinline__ void cpwait() {
    asm volatile("cp.async.wait_group %0;" :: "n"(N));
}

// ---------------- 0) transpose desc (1,D,H,W) -> (H*W, D) ----------------
__global__ void k_transpose(const float* __restrict__ d1,
                            const float* __restrict__ d2) {
    __shared__ float tile[32][33];
    const float* in = blockIdx.z ? d2 : d1;
    float* out = g_descT + (size_t)blockIdx.z * (HW*HW*DD);
    int p0 = blockIdx.x * 32, d0 = blockIdx.y * 32;
    int tx = threadIdx.x, ty = threadIdx.y;   // 32 x 8
    #pragma unroll
    for (int j = 0; j < 32; j += 8)
        tile[ty + j][tx] = in[(d0 + ty + j)*(HW*HW) + p0 + tx];
    __syncthreads();
    #pragma unroll
    for (int j = 0; j < 32; j += 8)
        out[(p0 + ty + j)*DD + d0 + tx] = tile[tx][ty + j];
}

// ---------------- 1) sample line points (XLA-exact: no FMA contraction) ----------------
__global__ void k_points(const float* __restrict__ seg1,
                         const float* __restrict__ seg2) {
    int l = blockIdx.x * blockDim.x + threadIdx.x;
    if (l >= 2*NL) return;
    const float* seg = (l < NL) ? (seg1 + l*4) : (seg2 + (l-NL)*4);
    float sy = seg[0], sx = seg[1], ey = seg[2], ex = seg[3];
    float dy = __fsub_rn(ey, sy), dx = __fsub_rn(ex, sx);
    float len = __fsqrt_rn(__fadd_rn(__fmul_rn(dy, dy), __fmul_rn(dx, dx)));
    float ns = floorf(__fdiv_rn(len, 8.0f));
    ns = fminf(fmaxf(ns, 2.0f), 5.0f);
    float den = __fsub_rn(ns, 1.0f);
    float ivy = __fdiv_rn(dy, den);
    float ivx = __fdiv_rn(dx, den);
    #pragma unroll
    for (int k = 0; k < S; k++) {
        bool v = ((float)k < ns);
        float py = __fadd_rn(sy, __fmul_rn((float)k, ivy));
        float px = __fadd_rn(sx, __fmul_rn((float)k, ivx));
        g_pts[(l*S + k)*2 + 0] = v ? py : 0.0f;
        g_pts[(l*S + k)*2 + 1] = v ? px : 0.0f;
        g_valid[l*S + k] = v ? 1 : 0;
    }
}

// ---------------- 2) bilinear sampling + L2 normalize (XLA-exact, coalesced) ----------------
__global__ void k_sample() {
    int p = blockIdx.x;              // 0..2*NS-1
    int d = threadIdx.x;             // 0..127
    int set = (p < NS) ? 0 : 1;
    int ps  = p - set*NS;
    const float* img = g_descT + (size_t)set * (HW*HW*DD);
    float py = g_pts[p*2 + 0];
    float px = g_pts[p*2 + 1];
    float xn = __fsub_rn(__fdiv_rn(__fmul_rn(2.0f, px), 511.0f), 1.0f);
    float yn = __fsub_rn(__fdiv_rn(__fmul_rn(2.0f, py), 511.0f), 1.0f);
    float ix = __fdiv_rn(__fsub_rn(__fmul_rn(__fadd_rn(xn, 1.0f), 128.0f), 1.0f), 2.0f);
    float iy = __fdiv_rn(__fsub_rn(__fmul_rn(__fadd_rn(yn, 1.0f), 128.0f), 1.0f), 2.0f);
    float x0f = floorf(ix), y0f = floorf(iy);
    float wx = __fsub_rn(ix, x0f), wy = __fsub_rn(iy, y0f);
    int x0 = (int)x0f, y0 = (int)y0f;
    int x1 = x0 + 1,  y1 = y0 + 1;

    float inb00 = ((x0 >= 0) & (x0 < HW) & (y0 >= 0) & (y0 < HW)) ? 1.0f : 0.0f;
    float inb10 = ((x1 >= 0) & (x1 < HW) & (y0 >= 0) & (y0 < HW)) ? 1.0f : 0.0f;
    float inb01 = ((x0 >= 0) & (x0 < HW) & (y1 >= 0) & (y1 < HW)) ? 1.0f : 0.0f;
    float inb11 = ((x1 >= 0) & (x1 < HW) & (y1 >= 0) & (y1 < HW)) ? 1.0f : 0.0f;
    int xc0 = min(max(x0, 0), HW-1), yc0 = min(max(y0, 0), HW-1);
    int xc1 = min(max(x1, 0), HW-1), yc1 = min(max(y1, 0), HW-1);

    float g00 = __fmul_rn(img[(yc0*HW + xc0)*DD + d], inb00);
    float g10 = __fmul_rn(img[(yc0*HW + xc1)*DD + d], inb10);
    float g01 = __fmul_rn(img[(yc1*HW + xc0)*DD + d], inb01);
    float g11 = __fmul_rn(img[(yc1*HW + xc1)*DD + d], inb11);

    float omx = __fsub_rn(1.0f, wx), omy = __fsub_rn(1.0f, wy);
    float w00 = __fmul_rn(omx, omy);
    float w10 = __fmul_rn(wx,  omy);
    float w01 = __fmul_rn(omx, wy);
    float w11 = __fmul_rn(wx,  wy);

    float m0 = __fmul_rn(g00, w00);
    float m1 = __fmul_rn(g10, w10);
    float m2 = __fmul_rn(g01, w01);
    float m3 = __fmul_rn(g11, w11);
    float v = __fadd_rn(__fadd_rn(__fadd_rn(m0, m1), m2), m3);

    __shared__ float sq[DD];
    __shared__ float s_nrm;
    sq[d] = __fmul_rn(v, v);
    __syncthreads();
    if (d < 32) {
        float partial = sq[d];
        partial = __fadd_rn(partial, sq[d + 32]);
        partial = __fadd_rn(partial, sq[d + 64]);
        partial = __fadd_rn(partial, sq[d + 96]);
        #pragma unroll
        for (int off = 16; off > 0; off >>= 1) {
            float o = __shfl_down_sync(0xffffffffu, partial, off);
            partial = __fadd_rn(partial, o);
        }
        if (d == 0) s_nrm = __fsqrt_rn(partial);
    }
    __syncthreads();
    float out = __fdiv_rn(v, s_nrm);
    g_desc[p*DD + d] = out;
    // k-major, slot-padded copy (exact same fp32 values)
    g_desck[set][d][ps + ps/5] = out;
}

// ---------------- 3) fused line_scores GEMM ----------------
// k-major double-buffered smem tiles filled via cp.async; AST=96 (vector fill).
// 128 threads: ti=tid>>3 (16 i-lines), tjq=tid&7 (8 j-pairs -> 16 j-lines).
#define KK  32
#define AST 96
#define NC  (DD/KK)   // 4 chunks

__global__ void __launch_bounds__(128) k_linescores() {
    __shared__ float As[2][KK*AST];
    __shared__ float Bs[2][KK*AST];
    __shared__ char  Av[80], Bv[80];

    int tid = threadIdx.x;           // 0..127
    int ti  = tid >> 3;              // 0..15
    int tjq = tid & 7;               // 0..7 (j-pair)
    int i0 = blockIdx.y * 16;
    int j0 = blockIdx.x * 16;

    if (tid < 80) {
        Av[tid] = (char)g_valid[i0*S + tid];
        Bv[tid] = (char)g_valid[NS + j0*S + tid];
    }

    // fill helper indices: 768 float4 per side per chunk, 6 per thread
    // idx -> row r = idx/24 (k within chunk), c4 = idx%24
    const float* Asrc = &g_desck[0][0][i0*6];
    const float* Bsrc = &g_desck[1][0][j0*6];
    unsigned aSm = smem_u32(As), bSm = smem_u32(Bs);

    #define FILL(chunk, buf)                                                   \
    {                                                                          \
        int kk_ = (chunk)*KK;                                                  \
        for (int idx = tid; idx < KK*24; idx += 128) {                         \
            int r = idx / 24, c4 = idx % 24;                                   \
            unsigned da = aSm + ((buf)*KK*AST + r*AST + c4*4)*4;               \
            unsigned db = bSm + ((buf)*KK*AST + r*AST + c4*4)*4;               \
            cpasync16(da, Asrc + (size_t)(kk_ + r)*CW + c4*4);                 \
            cpasync16(db, Bsrc + (size_t)(kk_ + r)*CW + c4*4);                 \
        }                                                                      \
        cpcommit();                                                            \
    }

    FILL(0, 0)
    FILL(1, 1)

    ull accM[2][S][2], accC[2][2];
    float acc44[2];
    #pragma unroll
    for (int jl = 0; jl < 2; jl++) {
        #pragma unroll
        for (int x = 0; x < S; x++) { accM[jl][x][0] = 0ull; accM[jl][x][1] = 0ull; }
        accC[jl][0] = 0ull; accC[jl][1] = 0ull;
        acc44[jl] = 0.0f;
    }

    unsigned aBase0 = aSm + (6*ti)*4;
    unsigned bBase0 = bSm + (6*(2*tjq))*4;

    #pragma unroll
    for (int c = 0; c < NC; c++) {
        int buf = c & 1;
        if (c < NC - 1) cpwait<1>(); else cpwait<0>();
        __syncthreads();

        unsigned aBase = aBase0 + buf*(KK*AST*4);
        unsigned bBase = bBase0 + buf*(KK*AST*4);
        #pragma unroll 8
        for (int k = 0; k < KK; k++) {
            unsigned ao = aBase + k*(AST*4);
            unsigned bo = bBase + k*(AST*4);
            float a0 = lds32(ao), a1 = lds32(ao+4), a2 = lds32(ao+8),
                  a3 = lds32(ao+12), a4 = lds32(ao+16);
            ull ad0 = pack2(a0,a0), ad1 = pack2(a1,a1), ad2 = pack2(a2,a2),
                ad3 = pack2(a3,a3), ad4 = pack2(a4,a4);
            ull ap01 = pack2(a0,a1), ap23 = pack2(a2,a3);

            #pragma unroll
            for (int jl = 0; jl < 2; jl++) {
                unsigned bj = bo + jl*24;
                ull bp01 = lds64(bj);
                ull bp23 = lds64(bj+8);
                float b4 = lds32(bj+16);
                ull b4d = pack2(b4,b4);

                fma2(accM[jl][0][0], ad0, bp01); fma2(accM[jl][0][1], ad0, bp23);
                fma2(accM[jl][1][0], ad1, bp01); fma2(accM[jl][1][1], ad1, bp23);
                fma2(accM[jl][2][0], ad2, bp01); fma2(accM[jl][2][1], ad2, bp23);
                fma2(accM[jl][3][0], ad3, bp01); fma2(accM[jl][3][1], ad3, bp23);
                fma2(accM[jl][4][0], ad4, bp01); fma2(accM[jl][4][1], ad4, bp23);
                fma2(accC[jl][0], ap01, b4d);
                fma2(accC[jl][1], ap23, b4d);
                acc44[jl] = __fmaf_rn(a4, b4, acc44[jl]);
            }
        }
        __syncthreads();
        if (c + 2 < NC) FILL(c + 2, buf)
    }
    #undef FILL

    bool va[S];
    #pragma unroll
    for (int r = 0; r < S; r++) va[r] = Av[ti*S + r] != 0;

    #pragma unroll
    for (int jl = 0; jl < 2; jl++) {
        int jloc = 2*tjq + jl;
        float acc[S][S];
        #pragma unroll
        for (int x = 0; x < S; x++) {
            float2 p01 = unpack2(accM[jl][x][0]);
            float2 p23 = unpack2(accM[jl][x][1]);
            acc[x][0] = p01.x; acc[x][1] = p01.y;
            acc[x][2] = p23.x; acc[x][3] = p23.y;
        }
        { float2 c0 = unpack2(accC[jl][0]); acc[0][4] = c0.x; acc[1][4] = c0.y; }
        { float2 c1 = unpack2(accC[jl][1]); acc[2][4] = c1.x; acc[3][4] = c1.y; }
        acc[4][4] = acc44[jl];

        bool vb[S];
        #pragma unroll
        for (int r = 0; r < S; r++) vb[r] = Bv[jloc*S + r] != 0;

        float blk[S][S];
        #pragma unroll
        for (int a = 0; a < S; a++)
            #pragma unroll
            for (int b = 0; b < S; b++)
                blk[a][b] = (va[a] && vb[b]) ? acc[a][b] : -1.0f;

        float s1 = 0.0f, c1 = 0.0f, s2 = 0.0f, c2 = 0.0f;
        #pragma unroll
        for (int a = 0; a < S; a++) {
            float m = -INFINITY;
            #pragma unroll
            for (int b = 0; b < S; b++) m = fmaxf(m, blk[a][b]);
            if (m != -1.0f) { s1 = __fadd_rn(s1, m); c1 = __fadd_rn(c1, 1.0f); }
        }
        #pragma unroll
        for (int b = 0; b < S; b++) {
            float m = -INFINITY;
            #pragma unroll
            for (int a = 0; a < S; a++) m = fmaxf(m, blk[a][b]);
            if (m != -1.0f) { s2 = __fadd_rn(s2, m); c2 = __fadd_rn(c2, 1.0f); }
        }
        float ls = __fdiv_rn(__fadd_rn(__fdiv_rn(s1, c1), __fdiv_rn(s2, c2)), 2.0f);
        int gi = i0 + ti, gj = j0 + jloc;
        g_ls [gi*NL + gj] = ls;
        g_lsT[gj*NL + gi] = ls;
    }
}

// ---------------- 4) top-K: warp per row ----------------
__global__ void k_topk() {
    int gwarp = (blockIdx.x * blockDim.x + threadIdx.x) >> 5;
    int lane  = threadIdx.x & 31;
    if (gwarp >= 2*NL) return;
    int dir = gwarp / NL, row = gwarp % NL;
    const float* src = dir ? &g_lsT[row*NL] : &g_ls[row*NL];

    float vals[NITER];
    #pragma unroll
    for (int i = 0; i < NITER; i++) {
        int j = lane + i*32;
        vals[i] = (j < NL) ? src[j] : -INFINITY;
    }

    float pv = INFINITY; int pj = 0x7fffffff;
    int* outp = &g_topk[dir*NL*TOPK + row*TOPK];

    for (int t = 0; t < TOPK; t++) {
        float bv = -INFINITY; int bj = -1;
        #pragma unroll
        for (int i = 0; i < NITER; i++) {
            int j = lane + i*32;
            float v = vals[i];
            bool elig = (v < pv) || (v == pv && j < pj);
            bool better = (v > bv) || (v == bv && j > bj);
            if (elig && better) { bv = v; bj = j; }
        }
        #pragma unroll
        for (int off = 16; off > 0; off >>= 1) {
            float ov = __shfl_down_sync(0xffffffffu, bv, off);
            int   oj = __shfl_down_sync(0xffffffffu, bj, off);
            if (ov > bv || (ov == bv && oj > bj)) { bv = ov; bj = oj; }
        }
        bv = __shfl_sync(0xffffffffu, bv, 0);
        bj = __shfl_sync(0xffffffffu, bj, 0);
        pv = bv; pj = bj;
        if (lane == 0) outp[TOPK - 1 - t] = bj;
    }
}

// ---------------- 5a) recompute 5x5 blocks: warp per (dir,row,t) ----------------
__global__ void k_nwdots() {
    int w = (blockIdx.x * blockDim.x + threadIdx.x) >> 5;
    int lane = threadIdx.x & 31;
    if (w >= 2*NL*TOPK) return;
    int dir = w / (NL*TOPK);
    int rem = w % (NL*TOPK);
    int row = rem / TOPK, t = rem % TOPK;
    int l = g_topk[dir*NL*TOPK + row*TOPK + t];
    int qs = dir ? (NS + row*S) : (row*S);
    int os = dir ? (l*S) : (NS + l*S);
    if (lane < 25) {
        int a = lane / 5, b = lane % 5;
        const float4* qp = (const float4*)&g_desc[(qs + a)*DD];
        const float4* op = (const float4*)&g_desc[(os + b)*DD];
        float acc = 0.0f;
        #pragma unroll 4
        for (int kq = 0; kq < DD/4; kq++) {
            float4 q4 = qp[kq], o4 = op[kq];
            acc = __fmaf_rn(q4.x, o4.x, acc);
            acc = __fmaf_rn(q4.y, o4.y, acc);
            acc = __fmaf_rn(q4.z, o4.z, acc);
            acc = __fmaf_rn(q4.w, o4.w, acc);
        }
        bool valid = g_valid[qs + a] && g_valid[os + b];
        g_sblk[w*25 + lane] = valid ? acc : -1.0f;
    }
}

// ---------------- 5b) NW DP + argmax: warp per (dir,row), lane per variant ----------------
__global__ void k_nwdp() {
    int gw = (blockIdx.x * blockDim.x + threadIdx.x) >> 5;
    int lane = threadIdx.x & 31;
    if (gw >= 2*NL) return;
    int dir = gw / NL, row = gw % NL;

    float nwv = -INFINITY;
    if (lane < 2*TOPK) {
        int tt = (lane < TOPK) ? lane : (lane - TOPK);
        bool flip = lane >= TOPK;
        const float* sb = &g_sblk[((dir*NL + row)*TOPK + tt)*25];
        float s[25];
        #pragma unroll
        for (int a = 0; a < 5; a++)
            #pragma unroll
            for (int b = 0; b < 5; b++)
                s[a*5 + b] = sb[a*5 + (flip ? (4 - b) : b)];

        float prev[6] = {0,0,0,0,0,0};
        #pragma unroll
        for (int a = 0; a < S; a++) {
            float nr[6]; nr[0] = 0.0f;
            float left = 0.0f;
            #pragma unroll
            for (int b = 0; b < S; b++) {
                float sc = __fsub_rn(s[a*5 + b], GAPP);
                float cur = fmaxf(fmaxf(left, prev[b+1]), __fadd_rn(prev[b], sc));
                nr[b+1] = cur; left = cur;
            }
            #pragma unroll
            for (int b = 0; b < 6; b++) prev[b] = nr[b];
        }
        nwv = prev[5];
    }

    float bv = nwv; int bi = (lane < 2*TOPK) ? lane : (1 << 30);
    #pragma unroll
    for (int off = 16; off > 0; off >>= 1) {
        float ov = __shfl_down_sync(0xffffffffu, bv, off);
        int   oi = __shfl_down_sync(0xffffffffu, bi, off);
        if (ov > bv || (ov == bv && oi < bi)) { bv = ov; bi = oi; }
    }
    bi = __shfl_sync(0xffffffffu, bi, 0);
    if (lane == 0)
        g_matches[dir*NL + row] = g_topk[dir*NL*TOPK + row*TOPK + (bi % TOPK)];
    if (dir == 0 && lane < 2*TOPK)
        g_nwout[row*2*TOPK + lane] = nwv;
}

// ---------------- 6) mutual check + write output ----------------
__global__ void k_final(float* __restrict__ out, int out_size) {
    int i = blockIdx.x * blockDim.x + threadIdx.x;
    if (i >= NL) return;
    int m1 = g_matches[i];
    int m2 = g_matches[NL + m1];
    int res = (m2 == i) ? m1 : -1;

    if (out_size >= NL + NL*2*TOPK) {
        out[i] = (float)res;
        for (int t = 0; t < 2*TOPK; t++)
            out[NL + i*2*TOPK + t] = g_nwout[i*2*TOPK + t];
    } else if (out_size == NL*2*TOPK) {
        for (int t = 0; t < 2*TOPK; t++)
            out[i*2*TOPK + t] = g_nwout[i*2*TOPK + t];
    } else {
        out[i] = (float)res;
    }
}

// ---------------- launch ----------------
extern "C" void kernel_launch(void* const* d_in, const int* in_sizes, int n_in,
                              void* d_out, int out_size) {
    (void)in_sizes; (void)n_in;
    const float* seg1  = (const float*)d_in[0];
    const float* seg2  = (const float*)d_in[1];
    const float* desc1 = (const float*)d_in[2];
    const float* desc2 = (const float*)d_in[3];

    k_transpose<<<dim3(HW*HW/32, DD/32, 2), dim3(32, 8)>>>(desc1, desc2);
    k_points<<<(2*NL + 255)/256, 256>>>(seg1, seg2);
    k_sample<<<2*NS, DD>>>();
    k_linescores<<<dim3(NL/16, NL/16), 128>>>();
    k_topk<<<(2*NL*32 + 255)/256, 256>>>();
    k_nwdots<<<(2*NL*TOPK*32 + 255)/256, 256>>>();
    k_nwdp<<<(2*NL*32 + 255)/256, 256>>>();
    k_final<<<(NL + 255)/256, 256>>>((float*)d_out, out_size);
}